// round 1
// baseline (speedup 1.0000x reference)
#include <cuda_runtime.h>
#include <math.h>

#define NN 100000
#define NE 800000

// ------------------------- scratch (static device globals) -------------------
__device__ float g_Q[(size_t)NN * 256];
__device__ float g_K[(size_t)NN * 256];
__device__ float g_V[(size_t)NN * 256];
__device__ float g_E[(size_t)NE * 256];
__device__ float g_H1[(size_t)NN * 256];
__device__ float g_H2[(size_t)NN * 256];
__device__ float g_alpha[NE];
__device__ int   g_mord[NN];
__device__ float g_ssum[NN];

// ------------------------- helpers ------------------------------------------
__device__ __forceinline__ int f2ord(float f) {
    int i = __float_as_int(f);
    return (i >= 0) ? i : (i ^ 0x7FFFFFFF);
}
__device__ __forceinline__ float ord2f(int i) {
    return __int_as_float((i >= 0) ? i : (i ^ 0x7FFFFFFF));
}

// ------------------------- SGEMM: C = A[MxK] @ B[KxN] + bias -----------------
// BM=BN=128, BK=8, 256 threads, 8x8 per thread. K % 8 == 0, N % 128 == 0.
__global__ __launch_bounds__(256) void sgemm_k(
    const float* __restrict__ A, const float* __restrict__ B,
    const float* __restrict__ bias, float* __restrict__ C,
    int M, int K, int N)
{
    __shared__ float As[8][128];
    __shared__ float Bs[8][128];

    const int t  = threadIdx.x;
    const int tx = t & 15;          // 0..15  (col group)
    const int ty = t >> 4;          // 0..15  (row group)
    const int rowBase = blockIdx.x * 128;
    const int colBase = blockIdx.y * 128;

    const int arow = t >> 1;        // 0..127
    const int acol = (t & 1) * 4;   // 0 or 4
    const int brow = t >> 5;        // 0..7
    const int bcol = (t & 31) * 4;  // 0..124

    float acc[8][8];
    #pragma unroll
    for (int i = 0; i < 8; i++)
        #pragma unroll
        for (int j = 0; j < 8; j++) acc[i][j] = 0.f;

    const float* Ab = A + (size_t)rowBase * K;
    const float* Bb = B + colBase;

    for (int kt = 0; kt < K; kt += 8) {
        float4 av = make_float4(0.f, 0.f, 0.f, 0.f);
        if (rowBase + arow < M)
            av = *(const float4*)(Ab + (size_t)arow * K + kt + acol);
        As[acol + 0][arow] = av.x;
        As[acol + 1][arow] = av.y;
        As[acol + 2][arow] = av.z;
        As[acol + 3][arow] = av.w;

        float4 bv = *(const float4*)(Bb + (size_t)(kt + brow) * N + bcol);
        *(float4*)&Bs[brow][bcol] = bv;

        __syncthreads();
        #pragma unroll
        for (int k = 0; k < 8; k++) {
            float a[8], b[8];
            #pragma unroll
            for (int i = 0; i < 8; i++) a[i] = As[k][ty * 8 + i];
            #pragma unroll
            for (int j = 0; j < 8; j++) b[j] = Bs[k][tx * 8 + j];
            #pragma unroll
            for (int i = 0; i < 8; i++)
                #pragma unroll
                for (int j = 0; j < 8; j++) acc[i][j] += a[i] * b[j];
        }
        __syncthreads();
    }

    #pragma unroll
    for (int i = 0; i < 8; i++) {
        int row = rowBase + ty * 8 + i;
        if (row < M) {
            #pragma unroll
            for (int j = 0; j < 8; j += 4) {
                int col = colBase + tx * 8 + j;
                float4 o;
                o.x = acc[i][j + 0] + bias[col + 0];
                o.y = acc[i][j + 1] + bias[col + 1];
                o.z = acc[i][j + 2] + bias[col + 2];
                o.w = acc[i][j + 3] + bias[col + 3];
                *(float4*)&C[(size_t)row * N + col] = o;
            }
        }
    }
}

// ------------------------- edge projection: E = attr[Ex16] @ We[16xC] --------
template <int C>
__global__ __launch_bounds__(256) void edge_proj_k(
    const float* __restrict__ attr, const float* __restrict__ We,
    float* __restrict__ E, int nE)
{
    __shared__ float Ws[16 * C];
    for (int i = threadIdx.x; i < 16 * C; i += blockDim.x) Ws[i] = We[i];
    __syncthreads();

    const int TPE = C / 4;                 // threads per edge
    const int epb = 256 / TPE;             // edges per block
    const int le  = threadIdx.x / TPE;
    const int lc  = threadIdx.x % TPE;
    const int e   = blockIdx.x * epb + le;
    if (e >= nE) return;

    float a[16];
    #pragma unroll
    for (int j4 = 0; j4 < 4; j4++) {
        float4 v = *(const float4*)(attr + (size_t)e * 16 + j4 * 4);
        a[j4 * 4 + 0] = v.x; a[j4 * 4 + 1] = v.y;
        a[j4 * 4 + 2] = v.z; a[j4 * 4 + 3] = v.w;
    }
    const int c0 = lc * 4;
    float4 acc = make_float4(0.f, 0.f, 0.f, 0.f);
    #pragma unroll
    for (int j = 0; j < 16; j++) {
        float4 w = *(const float4*)&Ws[j * C + c0];
        acc.x += a[j] * w.x; acc.y += a[j] * w.y;
        acc.z += a[j] * w.z; acc.w += a[j] * w.w;
    }
    *(float4*)&E[(size_t)e * C + c0] = acc;
}

// ------------------------- node init -----------------------------------------
__global__ void init_nodes_k(int* __restrict__ mord, float* __restrict__ ssum, int n)
{
    int i = blockIdx.x * blockDim.x + threadIdx.x;
    if (i < n) { mord[i] = 0x80000000; ssum[i] = 0.f; }
}

// ------------------------- alpha = <q[dst], k[src]+e>/sqrt(C); seg max -------
template <int C>
__global__ __launch_bounds__(256) void edge_alpha_k(
    const float* __restrict__ Q, const float* __restrict__ K,
    const float* __restrict__ E,
    const int* __restrict__ src, const int* __restrict__ dst,
    float* __restrict__ alpha, int* __restrict__ mord,
    int nE, float inv_sqrt_c)
{
    int w = (blockIdx.x * blockDim.x + threadIdx.x) >> 5;
    int lane = threadIdx.x & 31;
    if (w >= nE) return;
    const int s = src[w], d = dst[w];

    const float4* q4 = (const float4*)(Q + (size_t)d * C);
    const float4* k4 = (const float4*)(K + (size_t)s * C);
    const float4* e4 = (const float4*)(E + (size_t)w * C);

    float acc = 0.f;
    #pragma unroll
    for (int i = 0; i < C / 128; i++) {
        float4 q = q4[lane + i * 32];
        float4 k = k4[lane + i * 32];
        float4 e = e4[lane + i * 32];
        acc += q.x * (k.x + e.x) + q.y * (k.y + e.y)
             + q.z * (k.z + e.z) + q.w * (k.w + e.w);
    }
    #pragma unroll
    for (int off = 16; off; off >>= 1) acc += __shfl_xor_sync(0xFFFFFFFFu, acc, off);

    if (lane == 0) {
        float al = acc * inv_sqrt_c;
        alpha[w] = al;
        atomicMax(&mord[d], f2ord(al));
    }
}

// ------------------------- p = exp(alpha - m[dst]); seg sum ------------------
__global__ void edge_exp_k(
    float* __restrict__ alpha, const int* __restrict__ dst,
    const int* __restrict__ mord, float* __restrict__ ssum, int nE)
{
    int e = blockIdx.x * blockDim.x + threadIdx.x;
    if (e >= nE) return;
    int d = dst[e];
    float p = __expf(alpha[e] - ord2f(mord[d]));
    alpha[e] = p;
    atomicAdd(&ssum[d], p);
}

// ------------------------- Hout[dst] += a * (V[src] + E[e]) ------------------
template <int C>
__global__ __launch_bounds__(256) void edge_agg_k(
    const float* __restrict__ V, const float* __restrict__ E,
    const float* __restrict__ alpha, const float* __restrict__ ssum,
    const int* __restrict__ src, const int* __restrict__ dst,
    float* __restrict__ Hout, int nE)
{
    int w = (blockIdx.x * blockDim.x + threadIdx.x) >> 5;
    int lane = threadIdx.x & 31;
    if (w >= nE) return;
    const int s = src[w], d = dst[w];
    const float a = alpha[w] / (ssum[d] + 1e-16f);

    const float4* v4 = (const float4*)(V + (size_t)s * C);
    const float4* e4 = (const float4*)(E + (size_t)w * C);
    float* hb = Hout + (size_t)d * C;

    #pragma unroll
    for (int i = 0; i < C / 128; i++) {
        float4 v = v4[lane + i * 32];
        float4 e = e4[lane + i * 32];
        float x = a * (v.x + e.x);
        float y = a * (v.y + e.y);
        float z = a * (v.z + e.z);
        float ww = a * (v.w + e.w);
        float* p = hb + (lane + i * 32) * 4;
        asm volatile("red.global.add.v4.f32 [%0], {%1, %2, %3, %4};"
                     :: "l"(p), "f"(x), "f"(y), "f"(z), "f"(ww) : "memory");
    }
}

// ------------------------- relu in place -------------------------------------
__global__ void relu_k(float* __restrict__ h, size_t n)
{
    size_t i = (size_t)blockIdx.x * blockDim.x + threadIdx.x;
    if (i < n) h[i] = fmaxf(h[i], 0.f);
}

// ------------------------- classifier: out = H[Nx256]@Wc[256x10] + bc --------
__global__ __launch_bounds__(256) void classifier_k(
    const float* __restrict__ H, const float* __restrict__ Wc,
    const float* __restrict__ bc, float* __restrict__ out, int M)
{
    __shared__ float Ws[256 * 10];
    for (int i = threadIdx.x; i < 2560; i += blockDim.x) Ws[i] = Wc[i];
    __syncthreads();

    int row  = blockIdx.x * 8 + (threadIdx.x >> 5);
    int lane = threadIdx.x & 31;
    if (row >= M) return;

    float acc[10];
    #pragma unroll
    for (int c = 0; c < 10; c++) acc[c] = 0.f;

    for (int k = lane; k < 256; k += 32) {
        float h = H[(size_t)row * 256 + k];
        #pragma unroll
        for (int c = 0; c < 10; c++) acc[c] += h * Ws[k * 10 + c];
    }
    #pragma unroll
    for (int c = 0; c < 10; c++)
        #pragma unroll
        for (int off = 16; off; off >>= 1)
            acc[c] += __shfl_xor_sync(0xFFFFFFFFu, acc[c], off);

    if (lane == 0) {
        #pragma unroll
        for (int c = 0; c < 10; c++)
            out[(size_t)row * 10 + c] = acc[c] + bc[c];
    }
}

// ------------------------- launch --------------------------------------------
extern "C" void kernel_launch(void* const* d_in, const int* in_sizes, int n_in,
                              void* d_out, int out_size)
{
    const float* x    = (const float*)d_in[0];
    const int*   ei   = (const int*)d_in[1];
    const float* attr = (const float*)d_in[2];
    const int* src = ei;
    const int* dst = ei + NE;

    float *Q, *K, *V, *E, *H1, *H2, *alpha, *ssum; int* mord;
    cudaGetSymbolAddress((void**)&Q,     g_Q);
    cudaGetSymbolAddress((void**)&K,     g_K);
    cudaGetSymbolAddress((void**)&V,     g_V);
    cudaGetSymbolAddress((void**)&E,     g_E);
    cudaGetSymbolAddress((void**)&H1,    g_H1);
    cudaGetSymbolAddress((void**)&H2,    g_H2);
    cudaGetSymbolAddress((void**)&alpha, g_alpha);
    cudaGetSymbolAddress((void**)&mord,  g_mord);
    cudaGetSymbolAddress((void**)&ssum,  g_ssum);

    auto P = [&](int i) { return (const float*)d_in[i]; };

    const float* h = x;
    float* outbuf[3] = { H1, H2, H1 };
    int dins[3]  = { 128, 128, 128 };
    int couts[3] = { 128, 128, 256 };

    for (int l = 0; l < 3; l++) {
        const int base = 3 + l * 9;
        const float *Wq = P(base + 0), *bq = P(base + 1);
        const float *Wk = P(base + 2), *bk = P(base + 3);
        const float *Wv = P(base + 4), *bv = P(base + 5);
        const float *We = P(base + 6);
        const float *Ws = P(base + 7), *bs = P(base + 8);
        const int din = dins[l], C = couts[l];
        float* Hout = outbuf[l];

        dim3 gg((NN + 127) / 128, C / 128);
        sgemm_k<<<gg, 256>>>(h, Wq, bq, Q,    NN, din, C);
        sgemm_k<<<gg, 256>>>(h, Wk, bk, K,    NN, din, C);
        sgemm_k<<<gg, 256>>>(h, Wv, bv, V,    NN, din, C);
        sgemm_k<<<gg, 256>>>(h, Ws, bs, Hout, NN, din, C);  // skip into Hout

        if (C == 128) edge_proj_k<128><<<NE / 8, 256>>>(attr, We, E, NE);
        else          edge_proj_k<256><<<NE / 4, 256>>>(attr, We, E, NE);

        init_nodes_k<<<(NN + 255) / 256, 256>>>(mord, ssum, NN);

        float inv_sqrt_c = 1.0f / sqrtf((float)C);
        if (C == 128)
            edge_alpha_k<128><<<NE / 8, 256>>>(Q, K, E, src, dst, alpha, mord, NE, inv_sqrt_c);
        else
            edge_alpha_k<256><<<NE / 8, 256>>>(Q, K, E, src, dst, alpha, mord, NE, inv_sqrt_c);

        edge_exp_k<<<(NE + 255) / 256, 256>>>(alpha, dst, mord, ssum, NE);

        if (C == 128)
            edge_agg_k<128><<<NE / 8, 256>>>(V, E, alpha, ssum, src, dst, Hout, NE);
        else
            edge_agg_k<256><<<NE / 8, 256>>>(V, E, alpha, ssum, src, dst, Hout, NE);

        if (l < 2) {
            size_t n = (size_t)NN * C;
            relu_k<<<(unsigned)((n + 255) / 256), 256>>>(Hout, n);
        }
        h = Hout;
    }

    classifier_k<<<(NN + 7) / 8, 256>>>(outbuf[2], P(30), P(31), (float*)d_out, NN);
}

// round 3
// speedup vs baseline: 1.0717x; 1.0717x over previous
#include <cuda_runtime.h>
#include <math.h>

#define NN 100000
#define NE 800000

// ------------------------- scratch (static device globals) -------------------
__device__ float g_B1[(size_t)NN * 1024];   // QKVS buffer, layers 1 and 3
__device__ float g_B2[(size_t)NN * 512];    // QKVS buffer, layer 2
__device__ float g_P[(size_t)NN * 16];      // We @ q per node
__device__ float g_t[(size_t)NN * 16];      // sum_e a_e * attr_e per dst node
__device__ float g_alpha[NE];
__device__ int   g_mord[NN];
__device__ float g_ssum[NN];
__device__ float g_Wp[256 * 1024];          // packed [din, 4C] weights
__device__ float g_bp[1024];                // packed bias
__device__ float g_WeT[256 * 16];           // We transposed [C,16]

// ------------------------- helpers ------------------------------------------
__device__ __forceinline__ int f2ord(float f) {
    int i = __float_as_int(f);
    return (i >= 0) ? i : (i ^ 0x7FFFFFFF);
}
__device__ __forceinline__ float ord2f(int i) {
    return __int_as_float((i >= 0) ? i : (i ^ 0x7FFFFFFF));
}

// ------------------------- weight packer -------------------------------------
__global__ void pack_k(const float* __restrict__ Wq, const float* __restrict__ Wk,
                       const float* __restrict__ Wv, const float* __restrict__ Ws,
                       const float* __restrict__ bq, const float* __restrict__ bk,
                       const float* __restrict__ bv, const float* __restrict__ bs,
                       const float* __restrict__ We,
                       float* __restrict__ Wp, float* __restrict__ bp,
                       float* __restrict__ WeT, int din, int C)
{
    int N4 = 4 * C;
    int total = din * N4;
    for (int idx = blockIdx.x * blockDim.x + threadIdx.x; idx < total;
         idx += gridDim.x * blockDim.x) {
        int k = idx / N4, j = idx - k * N4;
        int sel = j / C, c = j - sel * C;
        const float* W = sel == 0 ? Wq : sel == 1 ? Wk : sel == 2 ? Wv : Ws;
        Wp[idx] = W[k * C + c];
        if (k == 0) {
            const float* bb = sel == 0 ? bq : sel == 1 ? bk : sel == 2 ? bv : bs;
            bp[j] = bb[c];
        }
        if (idx < 16 * C) {
            int f = idx / C, cc = idx - f * C;
            WeT[cc * 16 + f] = We[idx];
        }
    }
}

// ------------------------- SGEMM: C = A[MxK] @ B[KxN] + bias -----------------
// 128x128 tile, BK=16, double-buffered smem, 256 threads, 8x8/thread.
__global__ __launch_bounds__(256) void sgemm2_k(
    const float* __restrict__ A, int lda,
    const float* __restrict__ B, int ldb,
    const float* __restrict__ bias,
    float* __restrict__ Cmat, int ldc,
    int M, int K)
{
    __shared__ float As[2][16][132];   // padded, 16B-aligned rows
    __shared__ float Bs[2][16][128];

    const int t  = threadIdx.x;
    const int tx = t & 15;
    const int ty = t >> 4;
    const int rowBase = blockIdx.x * 128;
    const int colBase = blockIdx.y * 128;

    const int ar = t >> 2;            // 0..63
    const int kc = (t & 3) * 4;       // 0,4,8,12
    const int kb = t >> 5;            // 0..7
    const int cb = (t & 31) * 4;      // 0..124

    float acc[8][8];
    #pragma unroll
    for (int i = 0; i < 8; i++)
        #pragma unroll
        for (int j = 0; j < 8; j++) acc[i][j] = 0.f;

    const float4 z4 = make_float4(0.f, 0.f, 0.f, 0.f);
    float4 a0, a1, b0, b1;

    auto ldglob = [&](int kt) {
        int r0 = rowBase + ar, r1 = r0 + 64;
        a0 = (r0 < M) ? *(const float4*)(A + (size_t)r0 * lda + kt + kc) : z4;
        a1 = (r1 < M) ? *(const float4*)(A + (size_t)r1 * lda + kt + kc) : z4;
        b0 = *(const float4*)(B + (size_t)(kt + kb) * ldb + colBase + cb);
        b1 = *(const float4*)(B + (size_t)(kt + kb + 8) * ldb + colBase + cb);
    };
    auto stsh = [&](int buf) {
        As[buf][kc + 0][ar] = a0.x; As[buf][kc + 1][ar] = a0.y;
        As[buf][kc + 2][ar] = a0.z; As[buf][kc + 3][ar] = a0.w;
        As[buf][kc + 0][ar + 64] = a1.x; As[buf][kc + 1][ar + 64] = a1.y;
        As[buf][kc + 2][ar + 64] = a1.z; As[buf][kc + 3][ar + 64] = a1.w;
        *(float4*)&Bs[buf][kb][cb]     = b0;
        *(float4*)&Bs[buf][kb + 8][cb] = b1;
    };
    auto comp = [&](int buf) {
        #pragma unroll
        for (int k = 0; k < 16; k++) {
            float4 av0 = *(const float4*)&As[buf][k][ty * 4];
            float4 av1 = *(const float4*)&As[buf][k][64 + ty * 4];
            float4 bv0 = *(const float4*)&Bs[buf][k][tx * 4];
            float4 bv1 = *(const float4*)&Bs[buf][k][64 + tx * 4];
            float a[8] = {av0.x, av0.y, av0.z, av0.w, av1.x, av1.y, av1.z, av1.w};
            float b[8] = {bv0.x, bv0.y, bv0.z, bv0.w, bv1.x, bv1.y, bv1.z, bv1.w};
            #pragma unroll
            for (int i = 0; i < 8; i++)
                #pragma unroll
                for (int j = 0; j < 8; j++) acc[i][j] += a[i] * b[j];
        }
    };

    ldglob(0);
    stsh(0);
    __syncthreads();
    int buf = 0;
    for (int kt = 16; kt < K; kt += 16) {
        ldglob(kt);
        comp(buf);
        stsh(buf ^ 1);
        __syncthreads();
        buf ^= 1;
    }
    comp(buf);

    #pragma unroll
    for (int i = 0; i < 8; i++) {
        int row = rowBase + ((i < 4) ? (ty * 4 + i) : (64 + ty * 4 + i - 4));
        if (row < M) {
            #pragma unroll
            for (int jh = 0; jh < 2; jh++) {
                int col = colBase + jh * 64 + tx * 4;
                float4 o;
                o.x = acc[i][jh * 4 + 0] + bias[col + 0];
                o.y = acc[i][jh * 4 + 1] + bias[col + 1];
                o.z = acc[i][jh * 4 + 2] + bias[col + 2];
                o.w = acc[i][jh * 4 + 3] + bias[col + 3];
                *(float4*)&Cmat[(size_t)row * ldc + col] = o;
            }
        }
    }
}

// ------------------------- P[n,f] = sum_c Q[n,c] * We[f,c] -------------------
template <int C>
__global__ __launch_bounds__(256) void qe_k(
    const float* __restrict__ Q, int ld, const float* __restrict__ WeT,
    float* __restrict__ P, int n)
{
    __shared__ float WT[C * 16];
    for (int i = threadIdx.x; i < C * 16; i += 256) WT[i] = WeT[i];
    __syncthreads();

    int idx = blockIdx.x * 256 + threadIdx.x;
    int node = idx >> 4, f = idx & 15;
    if (node >= n) return;
    const float* q = Q + (size_t)node * ld;
    float acc = 0.f;
    #pragma unroll 8
    for (int c = 0; c < C; c++) acc += q[c] * WT[c * 16 + f];
    P[(size_t)node * 16 + f] = acc;
}

// ------------------------- node init -----------------------------------------
__global__ void init_nodes_k(int* __restrict__ mord, float* __restrict__ ssum,
                             float* __restrict__ t, int n)
{
    int i = blockIdx.x * blockDim.x + threadIdx.x;
    if (i < n) {
        mord[i] = 0x80000000;
        ssum[i] = 0.f;
        float4 z = make_float4(0.f, 0.f, 0.f, 0.f);
        float4* tp = (float4*)(t + (size_t)i * 16);
        tp[0] = z; tp[1] = z; tp[2] = z; tp[3] = z;
    }
}

// ------------------------- alpha + segment max -------------------------------
// alpha_e = (<q[dst],k[src]> + attr_e . P[dst]) / sqrt(C)
template <int C>
__global__ __launch_bounds__(256) void edge_alpha2_k(
    const float* __restrict__ QKVS, int ld,
    const float* __restrict__ attr, const float* __restrict__ P,
    const int* __restrict__ src, const int* __restrict__ dst,
    float* __restrict__ alpha, int* __restrict__ mord, int nE, float isc)
{
    int w = (blockIdx.x * blockDim.x + threadIdx.x) >> 5;
    int lane = threadIdx.x & 31;
    if (w >= nE) return;
    const int s = src[w], d = dst[w];

    const float4* q4 = (const float4*)(QKVS + (size_t)d * ld);
    const float4* k4 = (const float4*)(QKVS + (size_t)s * ld + C);

    float acc = 0.f;
    #pragma unroll
    for (int i = 0; i < C / 128; i++) {
        float4 q = q4[lane + i * 32];
        float4 k = k4[lane + i * 32];
        acc += q.x * k.x + q.y * k.y + q.z * k.z + q.w * k.w;
    }
    if (lane < 16)
        acc += attr[(size_t)w * 16 + lane] * P[(size_t)d * 16 + lane];

    #pragma unroll
    for (int off = 16; off; off >>= 1) acc += __shfl_xor_sync(0xFFFFFFFFu, acc, off);

    if (lane == 0) {
        float al = acc * isc;
        alpha[w] = al;
        atomicMax(&mord[d], f2ord(al));
    }
}

// ------------------------- p = exp(alpha - m[dst]); segment sum --------------
__global__ void edge_exp_k(
    float* __restrict__ alpha, const int* __restrict__ dst,
    const int* __restrict__ mord, float* __restrict__ ssum, int nE)
{
    int e = blockIdx.x * blockDim.x + threadIdx.x;
    if (e >= nE) return;
    int d = dst[e];
    float p = __expf(alpha[e] - ord2f(mord[d]));
    alpha[e] = p;
    atomicAdd(&ssum[d], p);
}

// ------------------------- aggregation ---------------------------------------
// H[dst] += a * V[src];  t[dst] += a * attr_e
template <int C>
__global__ __launch_bounds__(256) void edge_agg2_k(
    const float* __restrict__ QKVS, int ld,
    const float* __restrict__ attr,
    const float* __restrict__ alpha, const float* __restrict__ ssum,
    const int* __restrict__ src, const int* __restrict__ dst,
    float* __restrict__ Hbase, float* __restrict__ t, int nE)
{
    int w = (blockIdx.x * blockDim.x + threadIdx.x) >> 5;
    int lane = threadIdx.x & 31;
    if (w >= nE) return;
    const int s = src[w], d = dst[w];
    const float a = alpha[w] / (ssum[d] + 1e-16f);

    const float4* v4 = (const float4*)(QKVS + (size_t)s * ld + 2 * C);
    float* hb = Hbase + (size_t)d * ld;

    #pragma unroll
    for (int i = 0; i < C / 128; i++) {
        float4 v = v4[lane + i * 32];
        float x = a * v.x, y = a * v.y, z = a * v.z, ww = a * v.w;
        float* p = hb + (lane + i * 32) * 4;
        asm volatile("red.global.add.v4.f32 [%0], {%1, %2, %3, %4};"
                     :: "l"(p), "f"(x), "f"(y), "f"(z), "f"(ww) : "memory");
    }
    if (lane < 4) {
        float4 at = ((const float4*)(attr + (size_t)w * 16))[lane];
        float x = a * at.x, y = a * at.y, z = a * at.z, ww = a * at.w;
        float* p = t + (size_t)d * 16 + lane * 4;
        asm volatile("red.global.add.v4.f32 [%0], {%1, %2, %3, %4};"
                     :: "l"(p), "f"(x), "f"(y), "f"(z), "f"(ww) : "memory");
    }
}

// ------------------------- post: H += t @ We (+ relu) ------------------------
template <int C, bool RELU>
__global__ __launch_bounds__(256) void post_k(
    float* __restrict__ H, int ldh, const float* __restrict__ t,
    const float* __restrict__ We, int n)
{
    __shared__ float Ws[16 * C];
    for (int i = threadIdx.x; i < 16 * C; i += 256) Ws[i] = We[i];
    __syncthreads();

    const int TPN = C / 4;
    int node = blockIdx.x * (256 / TPN) + threadIdx.x / TPN;
    int c0 = (threadIdx.x % TPN) * 4;
    if (node >= n) return;

    const float* tn = t + (size_t)node * 16;
    float* hp = H + (size_t)node * ldh + c0;
    float4 acc = *(float4*)hp;
    #pragma unroll
    for (int f = 0; f < 16; f++) {
        float tf = tn[f];
        float4 w = *(const float4*)&Ws[f * C + c0];
        acc.x += tf * w.x; acc.y += tf * w.y;
        acc.z += tf * w.z; acc.w += tf * w.w;
    }
    if (RELU) {
        acc.x = fmaxf(acc.x, 0.f); acc.y = fmaxf(acc.y, 0.f);
        acc.z = fmaxf(acc.z, 0.f); acc.w = fmaxf(acc.w, 0.f);
    }
    *(float4*)hp = acc;
}

// ------------------------- classifier: out = H[Nx256]@Wc[256x10] + bc --------
__global__ __launch_bounds__(256) void classifier_k(
    const float* __restrict__ H, int ldh, const float* __restrict__ Wc,
    const float* __restrict__ bc, float* __restrict__ out, int M)
{
    __shared__ float Ws[256 * 10];
    for (int i = threadIdx.x; i < 2560; i += blockDim.x) Ws[i] = Wc[i];
    __syncthreads();

    int row  = blockIdx.x * 8 + (threadIdx.x >> 5);
    int lane = threadIdx.x & 31;
    if (row >= M) return;

    float acc[10];
    #pragma unroll
    for (int c = 0; c < 10; c++) acc[c] = 0.f;

    for (int k = lane; k < 256; k += 32) {
        float h = H[(size_t)row * ldh + k];
        #pragma unroll
        for (int c = 0; c < 10; c++) acc[c] += h * Ws[k * 10 + c];
    }
    #pragma unroll
    for (int c = 0; c < 10; c++)
        #pragma unroll
        for (int off = 16; off; off >>= 1)
            acc[c] += __shfl_xor_sync(0xFFFFFFFFu, acc[c], off);

    if (lane == 0) {
        #pragma unroll
        for (int c = 0; c < 10; c++)
            out[(size_t)row * 10 + c] = acc[c] + bc[c];
    }
}

// ------------------------- launch --------------------------------------------
extern "C" void kernel_launch(void* const* d_in, const int* in_sizes, int n_in,
                              void* d_out, int out_size)
{
    const float* x    = (const float*)d_in[0];
    const int*   ei   = (const int*)d_in[1];
    const float* attr = (const float*)d_in[2];
    const int* src = ei;
    const int* dst = ei + NE;

    float *B1, *B2, *P, *t, *alpha, *ssum, *Wp, *bp, *WeT; int* mord;
    cudaGetSymbolAddress((void**)&B1,    g_B1);
    cudaGetSymbolAddress((void**)&B2,    g_B2);
    cudaGetSymbolAddress((void**)&P,     g_P);
    cudaGetSymbolAddress((void**)&t,     g_t);
    cudaGetSymbolAddress((void**)&alpha, g_alpha);
    cudaGetSymbolAddress((void**)&mord,  g_mord);
    cudaGetSymbolAddress((void**)&ssum,  g_ssum);
    cudaGetSymbolAddress((void**)&Wp,    g_Wp);
    cudaGetSymbolAddress((void**)&bp,    g_bp);
    cudaGetSymbolAddress((void**)&WeT,   g_WeT);

    auto IN = [&](int i) { return (const float*)d_in[i]; };

    // layer configs
    const float* Ain[3]  = { x, B1 + 3 * 128, B2 + 3 * 128 };
    int          lda[3]  = { 128, 512, 512 };
    int          din[3]  = { 128, 128, 128 };
    int          Cc[3]   = { 128, 128, 256 };
    float*       outb[3] = { B1, B2, B1 };
    int          ldo[3]  = { 512, 512, 1024 };

    for (int l = 0; l < 3; l++) {
        const int base = 3 + l * 9;
        const float *Wq = IN(base + 0), *bq = IN(base + 1);
        const float *Wk = IN(base + 2), *bk = IN(base + 3);
        const float *Wv = IN(base + 4), *bv = IN(base + 5);
        const float *We = IN(base + 6);
        const float *Wr = IN(base + 7), *br = IN(base + 8);
        const int C = Cc[l];
        float* out = outb[l];
        const int ld = ldo[l];

        pack_k<<<256, 256>>>(Wq, Wk, Wv, Wr, bq, bk, bv, br, We,
                             Wp, bp, WeT, din[l], C);

        dim3 gg((NN + 127) / 128, 4 * C / 128);
        sgemm2_k<<<gg, 256>>>(Ain[l], lda[l], Wp, 4 * C, bp, out, ld, NN, din[l]);

        if (C == 128) qe_k<128><<<(NN * 16 + 255) / 256, 256>>>(out, ld, WeT, P, NN);
        else          qe_k<256><<<(NN * 16 + 255) / 256, 256>>>(out, ld, WeT, P, NN);

        init_nodes_k<<<(NN + 255) / 256, 256>>>(mord, ssum, t, NN);

        float isc = 1.0f / sqrtf((float)C);
        if (C == 128)
            edge_alpha2_k<128><<<NE / 8, 256>>>(out, ld, attr, P, src, dst, alpha, mord, NE, isc);
        else
            edge_alpha2_k<256><<<NE / 8, 256>>>(out, ld, attr, P, src, dst, alpha, mord, NE, isc);

        edge_exp_k<<<(NE + 255) / 256, 256>>>(alpha, dst, mord, ssum, NE);

        if (C == 128)
            edge_agg2_k<128><<<NE / 8, 256>>>(out, ld, attr, alpha, ssum, src, dst,
                                              out + 3 * C, t, NE);
        else
            edge_agg2_k<256><<<NE / 8, 256>>>(out, ld, attr, alpha, ssum, src, dst,
                                              out + 3 * C, t, NE);

        if (C == 128) {
            if (l < 2) post_k<128, true ><<<(NN + 7) / 8, 256>>>(out + 3 * C, ld, t, We, NN);
            else       post_k<128, false><<<(NN + 7) / 8, 256>>>(out + 3 * C, ld, t, We, NN);
        } else {
            if (l < 2) post_k<256, true ><<<(NN + 3) / 4, 256>>>(out + 3 * C, ld, t, We, NN);
            else       post_k<256, false><<<(NN + 3) / 4, 256>>>(out + 3 * C, ld, t, We, NN);
        }
    }

    classifier_k<<<(NN + 7) / 8, 256>>>(B1 + 768, 1024, IN(30), IN(31), (float*)d_out, NN);
}

// round 4
// speedup vs baseline: 1.9347x; 1.8052x over previous
#include <cuda_runtime.h>
#include <math.h>

#define NN 100000
#define NE 800000
#define SCAN_T 1024
#define SCAN_NB ((NN + SCAN_T - 1) / SCAN_T)

// ------------------------- scratch (static device globals) -------------------
__device__ float g_B1[(size_t)NN * 1024];   // QKVS buffer, layers 1 and 3
__device__ float g_B2[(size_t)NN * 512];    // QKVS buffer, layer 2
__device__ float g_P[(size_t)NN * 16];      // (We @ q) per node
__device__ float g_Wp[256 * 1024];          // packed [din, 4C] weights
__device__ float g_bp[1024];                // packed bias
__device__ float g_WeT[256 * 16];           // We transposed [C,16]
// sort scratch
__device__ int   g_cnt[NN];
__device__ int   g_off[NN + 1];
__device__ int   g_bsum[SCAN_NB + 1];
__device__ int   g_cursor[NN];
__device__ int   g_srcS[NE];
__device__ float g_attrS[(size_t)NE * 16];

// ------------------------- weight packer -------------------------------------
__global__ void pack_k(const float* __restrict__ Wq, const float* __restrict__ Wk,
                       const float* __restrict__ Wv, const float* __restrict__ Ws,
                       const float* __restrict__ bq, const float* __restrict__ bk,
                       const float* __restrict__ bv, const float* __restrict__ bs,
                       const float* __restrict__ We,
                       float* __restrict__ Wp, float* __restrict__ bp,
                       float* __restrict__ WeT, int din, int C)
{
    int N4 = 4 * C;
    int total = din * N4;
    for (int idx = blockIdx.x * blockDim.x + threadIdx.x; idx < total;
         idx += gridDim.x * blockDim.x) {
        int k = idx / N4, j = idx - k * N4;
        int sel = j / C, c = j - sel * C;
        const float* W = sel == 0 ? Wq : sel == 1 ? Wk : sel == 2 ? Wv : Ws;
        Wp[idx] = W[k * C + c];
        if (k == 0) {
            const float* bb = sel == 0 ? bq : sel == 1 ? bk : sel == 2 ? bv : bs;
            bp[j] = bb[c];
        }
        if (idx < 16 * C) {
            int f = idx / C, cc = idx - f * C;
            WeT[cc * 16 + f] = We[idx];
        }
    }
}

// ------------------------- sort: histogram / scan / scatter ------------------
__global__ void zero_cnt_k(int* __restrict__ cnt, int n)
{
    int i = blockIdx.x * blockDim.x + threadIdx.x;
    if (i < n) cnt[i] = 0;
}

__global__ void hist_k(const int* __restrict__ dst, int* __restrict__ cnt, int nE)
{
    int e = blockIdx.x * blockDim.x + threadIdx.x;
    if (e < nE) atomicAdd(&cnt[dst[e]], 1);
}

__global__ void scan1_k(const int* __restrict__ cnt, int* __restrict__ off,
                        int* __restrict__ bsum, int n)
{
    __shared__ int s[SCAN_T];
    int gid = blockIdx.x * SCAN_T + threadIdx.x;
    int v = (gid < n) ? cnt[gid] : 0;
    s[threadIdx.x] = v;
    __syncthreads();
    for (int d = 1; d < SCAN_T; d <<= 1) {
        int t = (threadIdx.x >= d) ? s[threadIdx.x - d] : 0;
        __syncthreads();
        s[threadIdx.x] += t;
        __syncthreads();
    }
    if (gid < n) off[gid] = s[threadIdx.x] - v;   // exclusive
    if (threadIdx.x == SCAN_T - 1) bsum[blockIdx.x] = s[threadIdx.x];
}

__global__ void scan2_k(int* __restrict__ bsum, int nb)
{
    __shared__ int s[128];
    int v = (threadIdx.x < nb) ? bsum[threadIdx.x] : 0;
    s[threadIdx.x] = v;
    __syncthreads();
    for (int d = 1; d < 128; d <<= 1) {
        int t = (threadIdx.x >= d) ? s[threadIdx.x - d] : 0;
        __syncthreads();
        s[threadIdx.x] += t;
        __syncthreads();
    }
    if (threadIdx.x < nb) bsum[threadIdx.x] = s[threadIdx.x] - v;   // exclusive
}

__global__ void scan3_k(int* __restrict__ off, const int* __restrict__ bsum,
                        int* __restrict__ cursor, int n, int total)
{
    int gid = blockIdx.x * SCAN_T + threadIdx.x;
    if (gid < n) {
        int o = off[gid] + bsum[blockIdx.x];
        off[gid] = o;
        cursor[gid] = o;
    }
    if (gid == 0) off[n] = total;
}

__global__ void scatter_k(const int* __restrict__ src, const int* __restrict__ dst,
                          const float* __restrict__ attr, int* __restrict__ cursor,
                          int* __restrict__ srcS, float* __restrict__ attrS, int nE)
{
    int e = blockIdx.x * blockDim.x + threadIdx.x;
    if (e >= nE) return;
    int pos = atomicAdd(&cursor[dst[e]], 1);
    srcS[pos] = src[e];
    const float4* a4 = (const float4*)(attr + (size_t)e * 16);
    float4* o4 = (float4*)(attrS + (size_t)pos * 16);
    o4[0] = a4[0]; o4[1] = a4[1]; o4[2] = a4[2]; o4[3] = a4[3];
}

// ------------------------- SGEMM: C = A[MxK] @ B[KxN] + bias -----------------
// 128x128 tile, BK=16, double-buffered smem, 256 threads, 8x8/thread.
__global__ __launch_bounds__(256) void sgemm2_k(
    const float* __restrict__ A, int lda,
    const float* __restrict__ B, int ldb,
    const float* __restrict__ bias,
    float* __restrict__ Cmat, int ldc,
    int M, int K)
{
    __shared__ float As[2][16][132];
    __shared__ float Bs[2][16][128];

    const int t  = threadIdx.x;
    const int tx = t & 15;
    const int ty = t >> 4;
    const int rowBase = blockIdx.x * 128;
    const int colBase = blockIdx.y * 128;

    const int ar = t >> 2;
    const int kc = (t & 3) * 4;
    const int kb = t >> 5;
    const int cb = (t & 31) * 4;

    float acc[8][8];
    #pragma unroll
    for (int i = 0; i < 8; i++)
        #pragma unroll
        for (int j = 0; j < 8; j++) acc[i][j] = 0.f;

    const float4 z4 = make_float4(0.f, 0.f, 0.f, 0.f);
    float4 a0, a1, b0, b1;

    auto ldglob = [&](int kt) {
        int r0 = rowBase + ar, r1 = r0 + 64;
        a0 = (r0 < M) ? *(const float4*)(A + (size_t)r0 * lda + kt + kc) : z4;
        a1 = (r1 < M) ? *(const float4*)(A + (size_t)r1 * lda + kt + kc) : z4;
        b0 = *(const float4*)(B + (size_t)(kt + kb) * ldb + colBase + cb);
        b1 = *(const float4*)(B + (size_t)(kt + kb + 8) * ldb + colBase + cb);
    };
    auto stsh = [&](int buf) {
        As[buf][kc + 0][ar] = a0.x; As[buf][kc + 1][ar] = a0.y;
        As[buf][kc + 2][ar] = a0.z; As[buf][kc + 3][ar] = a0.w;
        As[buf][kc + 0][ar + 64] = a1.x; As[buf][kc + 1][ar + 64] = a1.y;
        As[buf][kc + 2][ar + 64] = a1.z; As[buf][kc + 3][ar + 64] = a1.w;
        *(float4*)&Bs[buf][kb][cb]     = b0;
        *(float4*)&Bs[buf][kb + 8][cb] = b1;
    };
    auto comp = [&](int buf) {
        #pragma unroll
        for (int k = 0; k < 16; k++) {
            float4 av0 = *(const float4*)&As[buf][k][ty * 4];
            float4 av1 = *(const float4*)&As[buf][k][64 + ty * 4];
            float4 bv0 = *(const float4*)&Bs[buf][k][tx * 4];
            float4 bv1 = *(const float4*)&Bs[buf][k][64 + tx * 4];
            float a[8] = {av0.x, av0.y, av0.z, av0.w, av1.x, av1.y, av1.z, av1.w};
            float b[8] = {bv0.x, bv0.y, bv0.z, bv0.w, bv1.x, bv1.y, bv1.z, bv1.w};
            #pragma unroll
            for (int i = 0; i < 8; i++)
                #pragma unroll
                for (int j = 0; j < 8; j++) acc[i][j] += a[i] * b[j];
        }
    };

    ldglob(0);
    stsh(0);
    __syncthreads();
    int buf = 0;
    for (int kt = 16; kt < K; kt += 16) {
        ldglob(kt);
        comp(buf);
        stsh(buf ^ 1);
        __syncthreads();
        buf ^= 1;
    }
    comp(buf);

    #pragma unroll
    for (int i = 0; i < 8; i++) {
        int row = rowBase + ((i < 4) ? (ty * 4 + i) : (64 + ty * 4 + i - 4));
        if (row < M) {
            #pragma unroll
            for (int jh = 0; jh < 2; jh++) {
                int col = colBase + jh * 64 + tx * 4;
                float4 o;
                o.x = acc[i][jh * 4 + 0] + bias[col + 0];
                o.y = acc[i][jh * 4 + 1] + bias[col + 1];
                o.z = acc[i][jh * 4 + 2] + bias[col + 2];
                o.w = acc[i][jh * 4 + 3] + bias[col + 3];
                *(float4*)&Cmat[(size_t)row * ldc + col] = o;
            }
        }
    }
}

// ------------------------- P[n,f] = sum_c Q[n,c] * We[f,c] -------------------
template <int C>
__global__ __launch_bounds__(256) void qe_k(
    const float* __restrict__ Q, int ld, const float* __restrict__ WeT,
    float* __restrict__ P, int n)
{
    __shared__ float WT[C * 16];
    for (int i = threadIdx.x; i < C * 16; i += 256) WT[i] = WeT[i];
    __syncthreads();

    int idx = blockIdx.x * 256 + threadIdx.x;
    int node = idx >> 4, f = idx & 15;
    if (node >= n) return;
    const float* q = Q + (size_t)node * ld;
    float acc = 0.f;
    #pragma unroll 8
    for (int c = 0; c < C; c++) acc += q[c] * WT[c * 16 + f];
    P[(size_t)node * 16 + f] = acc;
}

// ------------------------- fused attention (warp per dst node) ---------------
// One pass over sorted edges with online softmax:
//   alpha_e = (<q[d], k[src]> + attr_e . P[d]) / sqrt(C)
//   H[d] = skip[d] + (sum p*v[src]) / s + ((sum p*attr_e)/s) @ We     (+relu)
template <int C, bool RELU>
__global__ __launch_bounds__(256) void fused_attn_k(
    float* __restrict__ QKVS, int ld,
    const float* __restrict__ attrS, const int* __restrict__ srcS,
    const int* __restrict__ off, const float* __restrict__ P,
    const float* __restrict__ We, float isc, int n)
{
    constexpr int NV = C / 128;           // float4 vectors per lane
    __shared__ float Ws[16 * C];
    for (int i = threadIdx.x; i < 16 * C; i += 256) Ws[i] = We[i];
    __syncthreads();

    const int node = blockIdx.x * 8 + (threadIdx.x >> 5);
    const int lane = threadIdx.x & 31;
    if (node >= n) return;

    const int e0 = off[node], e1 = off[node + 1];

    float4 q[NV];
    const float4* qb = (const float4*)(QKVS + (size_t)node * ld);
    #pragma unroll
    for (int i = 0; i < NV; i++) q[i] = qb[lane + i * 32];

    const float pP = (lane < 16) ? P[(size_t)node * 16 + lane] : 0.f;

    float m = -INFINITY, s = 0.f, tacc = 0.f;
    float4 vacc[NV];
    #pragma unroll
    for (int i = 0; i < NV; i++) vacc[i] = make_float4(0.f, 0.f, 0.f, 0.f);

    for (int e = e0; e < e1; e++) {
        const int sn = srcS[e];
        const float av = (lane < 16) ? attrS[(size_t)e * 16 + lane] : 0.f;
        const float4* kb = (const float4*)(QKVS + (size_t)sn * ld + C);
        const float4* vb = (const float4*)(QKVS + (size_t)sn * ld + 2 * C);

        float4 kv[NV], vv[NV];
        #pragma unroll
        for (int i = 0; i < NV; i++) { kv[i] = kb[lane + i * 32]; vv[i] = vb[lane + i * 32]; }

        float part = av * pP;
        #pragma unroll
        for (int i = 0; i < NV; i++)
            part += q[i].x * kv[i].x + q[i].y * kv[i].y
                  + q[i].z * kv[i].z + q[i].w * kv[i].w;
        #pragma unroll
        for (int o = 16; o; o >>= 1) part += __shfl_xor_sync(0xFFFFFFFFu, part, o);

        const float al = part * isc;
        const float mn = fmaxf(m, al);
        const float corr = __expf(m - mn);
        const float p = __expf(al - mn);
        m = mn;
        s = s * corr + p;
        tacc = tacc * corr + p * av;
        #pragma unroll
        for (int i = 0; i < NV; i++) {
            vacc[i].x = vacc[i].x * corr + p * vv[i].x;
            vacc[i].y = vacc[i].y * corr + p * vv[i].y;
            vacc[i].z = vacc[i].z * corr + p * vv[i].z;
            vacc[i].w = vacc[i].w * corr + p * vv[i].w;
        }
    }

    const float inv = 1.f / (s + 1e-16f);

    float4 ed[NV];
    #pragma unroll
    for (int i = 0; i < NV; i++) ed[i] = make_float4(0.f, 0.f, 0.f, 0.f);
    #pragma unroll
    for (int f = 0; f < 16; f++) {
        const float tf = __shfl_sync(0xFFFFFFFFu, tacc, f) * inv;
        #pragma unroll
        for (int i = 0; i < NV; i++) {
            float4 w = *(const float4*)&Ws[f * C + (lane + i * 32) * 4];
            ed[i].x += tf * w.x; ed[i].y += tf * w.y;
            ed[i].z += tf * w.z; ed[i].w += tf * w.w;
        }
    }

    float4* hb = (float4*)(QKVS + (size_t)node * ld + 3 * C);
    #pragma unroll
    for (int i = 0; i < NV; i++) {
        float4 sk = hb[lane + i * 32];
        float4 o;
        o.x = sk.x + vacc[i].x * inv + ed[i].x;
        o.y = sk.y + vacc[i].y * inv + ed[i].y;
        o.z = sk.z + vacc[i].z * inv + ed[i].z;
        o.w = sk.w + vacc[i].w * inv + ed[i].w;
        if (RELU) {
            o.x = fmaxf(o.x, 0.f); o.y = fmaxf(o.y, 0.f);
            o.z = fmaxf(o.z, 0.f); o.w = fmaxf(o.w, 0.f);
        }
        hb[lane + i * 32] = o;
    }
}

// ------------------------- classifier: out = H[Nx256]@Wc[256x10] + bc --------
__global__ __launch_bounds__(256) void classifier_k(
    const float* __restrict__ H, int ldh, const float* __restrict__ Wc,
    const float* __restrict__ bc, float* __restrict__ out, int M)
{
    __shared__ float Ws[256 * 10];
    for (int i = threadIdx.x; i < 2560; i += blockDim.x) Ws[i] = Wc[i];
    __syncthreads();

    int row  = blockIdx.x * 8 + (threadIdx.x >> 5);
    int lane = threadIdx.x & 31;
    if (row >= M) return;

    float acc[10];
    #pragma unroll
    for (int c = 0; c < 10; c++) acc[c] = 0.f;

    for (int k = lane; k < 256; k += 32) {
        float h = H[(size_t)row * ldh + k];
        #pragma unroll
        for (int c = 0; c < 10; c++) acc[c] += h * Ws[k * 10 + c];
    }
    #pragma unroll
    for (int c = 0; c < 10; c++)
        #pragma unroll
        for (int o = 16; o; o >>= 1)
            acc[c] += __shfl_xor_sync(0xFFFFFFFFu, acc[c], o);

    if (lane == 0) {
        #pragma unroll
        for (int c = 0; c < 10; c++)
            out[(size_t)row * 10 + c] = acc[c] + bc[c];
    }
}

// ------------------------- launch --------------------------------------------
extern "C" void kernel_launch(void* const* d_in, const int* in_sizes, int n_in,
                              void* d_out, int out_size)
{
    const float* x    = (const float*)d_in[0];
    const int*   ei   = (const int*)d_in[1];
    const float* attr = (const float*)d_in[2];
    const int* src = ei;
    const int* dst = ei + NE;

    float *B1, *B2, *P, *Wp, *bp, *WeT, *attrS;
    int *cnt, *off, *bsum, *cursor, *srcS;
    cudaGetSymbolAddress((void**)&B1,     g_B1);
    cudaGetSymbolAddress((void**)&B2,     g_B2);
    cudaGetSymbolAddress((void**)&P,      g_P);
    cudaGetSymbolAddress((void**)&Wp,     g_Wp);
    cudaGetSymbolAddress((void**)&bp,     g_bp);
    cudaGetSymbolAddress((void**)&WeT,    g_WeT);
    cudaGetSymbolAddress((void**)&cnt,    g_cnt);
    cudaGetSymbolAddress((void**)&off,    g_off);
    cudaGetSymbolAddress((void**)&bsum,   g_bsum);
    cudaGetSymbolAddress((void**)&cursor, g_cursor);
    cudaGetSymbolAddress((void**)&srcS,   g_srcS);
    cudaGetSymbolAddress((void**)&attrS,  g_attrS);

    auto IN = [&](int i) { return (const float*)d_in[i]; };

    // ---- sort edges by dst (once; reused by all 3 layers) ----
    zero_cnt_k<<<(NN + 255) / 256, 256>>>(cnt, NN);
    hist_k<<<(NE + 255) / 256, 256>>>(dst, cnt, NE);
    scan1_k<<<SCAN_NB, SCAN_T>>>(cnt, off, bsum, NN);
    scan2_k<<<1, 128>>>(bsum, SCAN_NB);
    scan3_k<<<SCAN_NB, SCAN_T>>>(off, bsum, cursor, NN, NE);
    scatter_k<<<(NE + 255) / 256, 256>>>(src, dst, attr, cursor, srcS, attrS, NE);

    // ---- layers ----
    const float* Ain[3]  = { x, B1 + 3 * 128, B2 + 3 * 128 };
    int          lda[3]  = { 128, 512, 512 };
    int          din[3]  = { 128, 128, 128 };
    int          Cc[3]   = { 128, 128, 256 };
    float*       outb[3] = { B1, B2, B1 };
    int          ldo[3]  = { 512, 512, 1024 };

    for (int l = 0; l < 3; l++) {
        const int base = 3 + l * 9;
        const float *Wq = IN(base + 0), *bq = IN(base + 1);
        const float *Wk = IN(base + 2), *bk = IN(base + 3);
        const float *Wv = IN(base + 4), *bv = IN(base + 5);
        const float *We = IN(base + 6);
        const float *Wr = IN(base + 7), *br = IN(base + 8);
        const int C = Cc[l];
        float* out = outb[l];
        const int ld = ldo[l];

        pack_k<<<256, 256>>>(Wq, Wk, Wv, Wr, bq, bk, bv, br, We,
                             Wp, bp, WeT, din[l], C);

        dim3 gg((NN + 127) / 128, 4 * C / 128);
        sgemm2_k<<<gg, 256>>>(Ain[l], lda[l], Wp, 4 * C, bp, out, ld, NN, din[l]);

        if (C == 128) qe_k<128><<<(NN * 16 + 255) / 256, 256>>>(out, ld, WeT, P, NN);
        else          qe_k<256><<<(NN * 16 + 255) / 256, 256>>>(out, ld, WeT, P, NN);

        float isc = 1.0f / sqrtf((float)C);
        if (C == 128) {
            if (l < 2)
                fused_attn_k<128, true ><<<(NN + 7) / 8, 256>>>(out, ld, attrS, srcS, off, P, We, isc, NN);
            else
                fused_attn_k<128, false><<<(NN + 7) / 8, 256>>>(out, ld, attrS, srcS, off, P, We, isc, NN);
        } else {
            if (l < 2)
                fused_attn_k<256, true ><<<(NN + 7) / 8, 256>>>(out, ld, attrS, srcS, off, P, We, isc, NN);
            else
                fused_attn_k<256, false><<<(NN + 7) / 8, 256>>>(out, ld, attrS, srcS, off, P, We, isc, NN);
        }
    }

    classifier_k<<<(NN + 7) / 8, 256>>>(B1 + 768, 1024, IN(30), IN(31), (float*)d_out, NN);
}

// round 5
// speedup vs baseline: 2.5842x; 1.3357x over previous
#include <cuda_runtime.h>
#include <math.h>

#define NN 100000
#define NE 800000
#define SCAN_T 1024
#define SCAN_NB ((NN + SCAN_T - 1) / SCAN_T)

// ------------------------- scratch (static device globals) -------------------
__device__ float g_B1[(size_t)NN * 1024];
__device__ float g_B2[(size_t)NN * 512];
__device__ float g_P[(size_t)NN * 16];
__device__ float g_Wp[256 * 1024];
__device__ float g_bp[1024];
__device__ float g_WeT[256 * 16];
__device__ int   g_cnt[NN];
__device__ int   g_off[NN + 1];
__device__ int   g_bsum[SCAN_NB + 1];
__device__ int   g_cursor[NN];
__device__ int   g_srcS[NE];
__device__ float g_attrS[(size_t)NE * 16];

// ------------------------- helpers ------------------------------------------
__device__ __forceinline__ unsigned tf32(float x) {
    unsigned u;
    asm("cvt.rna.tf32.f32 %0, %1;" : "=r"(u) : "f"(x));
    return u;
}

__device__ __forceinline__ void mma_tf32(float* c, const unsigned* a, const unsigned* b) {
    asm volatile(
        "mma.sync.aligned.m16n8k8.row.col.f32.tf32.tf32.f32 "
        "{%0,%1,%2,%3}, {%4,%5,%6,%7}, {%8,%9}, {%0,%1,%2,%3};"
        : "+f"(c[0]), "+f"(c[1]), "+f"(c[2]), "+f"(c[3])
        : "r"(a[0]), "r"(a[1]), "r"(a[2]), "r"(a[3]), "r"(b[0]), "r"(b[1]));
}

// ------------------------- weight packer -------------------------------------
__global__ void pack_k(const float* __restrict__ Wq, const float* __restrict__ Wk,
                       const float* __restrict__ Wv, const float* __restrict__ Ws,
                       const float* __restrict__ bq, const float* __restrict__ bk,
                       const float* __restrict__ bv, const float* __restrict__ bs,
                       const float* __restrict__ We,
                       float* __restrict__ Wp, float* __restrict__ bp,
                       float* __restrict__ WeT, int din, int C)
{
    int N4 = 4 * C;
    int total = din * N4;
    for (int idx = blockIdx.x * blockDim.x + threadIdx.x; idx < total;
         idx += gridDim.x * blockDim.x) {
        int k = idx / N4, j = idx - k * N4;
        int sel = j / C, c = j - sel * C;
        const float* W = sel == 0 ? Wq : sel == 1 ? Wk : sel == 2 ? Wv : Ws;
        Wp[idx] = W[k * C + c];
        if (k == 0) {
            const float* bb = sel == 0 ? bq : sel == 1 ? bk : sel == 2 ? bv : bs;
            bp[j] = bb[c];
        }
        if (idx < 16 * C) {
            int f = idx / C, cc = idx - f * C;
            WeT[cc * 16 + f] = We[idx];
        }
    }
}

// ------------------------- sort: histogram / scan / scatter ------------------
__global__ void zero_cnt_k(int* __restrict__ cnt, int n)
{
    int i = blockIdx.x * blockDim.x + threadIdx.x;
    if (i < n) cnt[i] = 0;
}

__global__ void hist_k(const int* __restrict__ dst, int* __restrict__ cnt, int nE)
{
    int e = blockIdx.x * blockDim.x + threadIdx.x;
    if (e < nE) atomicAdd(&cnt[dst[e]], 1);
}

__global__ void scan1_k(const int* __restrict__ cnt, int* __restrict__ off,
                        int* __restrict__ bsum, int n)
{
    __shared__ int s[SCAN_T];
    int gid = blockIdx.x * SCAN_T + threadIdx.x;
    int v = (gid < n) ? cnt[gid] : 0;
    s[threadIdx.x] = v;
    __syncthreads();
    for (int d = 1; d < SCAN_T; d <<= 1) {
        int t = (threadIdx.x >= d) ? s[threadIdx.x - d] : 0;
        __syncthreads();
        s[threadIdx.x] += t;
        __syncthreads();
    }
    if (gid < n) off[gid] = s[threadIdx.x] - v;
    if (threadIdx.x == SCAN_T - 1) bsum[blockIdx.x] = s[threadIdx.x];
}

__global__ void scan2_k(int* __restrict__ bsum, int nb)
{
    __shared__ int s[128];
    int v = (threadIdx.x < nb) ? bsum[threadIdx.x] : 0;
    s[threadIdx.x] = v;
    __syncthreads();
    for (int d = 1; d < 128; d <<= 1) {
        int t = (threadIdx.x >= d) ? s[threadIdx.x - d] : 0;
        __syncthreads();
        s[threadIdx.x] += t;
        __syncthreads();
    }
    if (threadIdx.x < nb) bsum[threadIdx.x] = s[threadIdx.x] - v;
}

__global__ void scan3_k(int* __restrict__ off, const int* __restrict__ bsum,
                        int* __restrict__ cursor, int n, int total)
{
    int gid = blockIdx.x * SCAN_T + threadIdx.x;
    if (gid < n) {
        int o = off[gid] + bsum[blockIdx.x];
        off[gid] = o;
        cursor[gid] = o;
    }
    if (gid == 0) off[n] = total;
}

__global__ void scatter_k(const int* __restrict__ src, const int* __restrict__ dst,
                          const float* __restrict__ attr, int* __restrict__ cursor,
                          int* __restrict__ srcS, float* __restrict__ attrS, int nE)
{
    int e = blockIdx.x * blockDim.x + threadIdx.x;
    if (e >= nE) return;
    int pos = atomicAdd(&cursor[dst[e]], 1);
    srcS[pos] = src[e];
    const float4* a4 = (const float4*)(attr + (size_t)e * 16);
    float4* o4 = (float4*)(attrS + (size_t)pos * 16);
    o4[0] = a4[0]; o4[1] = a4[1]; o4[2] = a4[2]; o4[3] = a4[3];
}

// ------------------------- TF32 tensor-core GEMM -----------------------------
// C = A[MxK] @ B[KxN] + bias. 128x128 tile, BK=16 double buffered,
// 8 warps, each 64x32 via 4x4 grid of m16n8k8 mma. K % 16 == 0, N % 128 == 0.
__global__ __launch_bounds__(256, 2) void sgemm_tc_k(
    const float* __restrict__ A, int lda,
    const float* __restrict__ B, int ldb,
    const float* __restrict__ bias,
    float* __restrict__ Cmat, int ldc,
    int M, int K)
{
    __shared__ unsigned As[2][16][136];
    __shared__ unsigned Bs[2][16][136];

    const int t    = threadIdx.x;
    const int wid  = t >> 5;
    const int lane = t & 31;
    const int tg   = lane & 3;     // k-sub within fragment
    const int gi   = lane >> 2;    // row/col group
    const int wm   = (wid >> 2) * 64;
    const int wn   = (wid & 3) * 32;
    const int rowBase = blockIdx.x * 128;
    const int colBase = blockIdx.y * 128;

    const int ar = t >> 2;          // 0..63
    const int kc = (t & 3) * 4;     // 0,4,8,12
    const int kb = t >> 5;          // 0..7
    const int cb = (t & 31) * 4;    // 0..124

    float acc[4][4][4];
    #pragma unroll
    for (int mi = 0; mi < 4; mi++)
        #pragma unroll
        for (int ni = 0; ni < 4; ni++)
            #pragma unroll
            for (int c = 0; c < 4; c++) acc[mi][ni][c] = 0.f;

    const float4 z4 = make_float4(0.f, 0.f, 0.f, 0.f);
    float4 a0, a1, b0, b1;

    auto ldglob = [&](int kt) {
        int r0 = rowBase + ar, r1 = r0 + 64;
        a0 = (r0 < M) ? *(const float4*)(A + (size_t)r0 * lda + kt + kc) : z4;
        a1 = (r1 < M) ? *(const float4*)(A + (size_t)r1 * lda + kt + kc) : z4;
        b0 = *(const float4*)(B + (size_t)(kt + kb) * ldb + colBase + cb);
        b1 = *(const float4*)(B + (size_t)(kt + kb + 8) * ldb + colBase + cb);
    };
    auto stsh = [&](int buf) {
        As[buf][kc + 0][ar] = tf32(a0.x); As[buf][kc + 1][ar] = tf32(a0.y);
        As[buf][kc + 2][ar] = tf32(a0.z); As[buf][kc + 3][ar] = tf32(a0.w);
        As[buf][kc + 0][ar + 64] = tf32(a1.x); As[buf][kc + 1][ar + 64] = tf32(a1.y);
        As[buf][kc + 2][ar + 64] = tf32(a1.z); As[buf][kc + 3][ar + 64] = tf32(a1.w);
        Bs[buf][kb][cb + 0] = tf32(b0.x); Bs[buf][kb][cb + 1] = tf32(b0.y);
        Bs[buf][kb][cb + 2] = tf32(b0.z); Bs[buf][kb][cb + 3] = tf32(b0.w);
        Bs[buf][kb + 8][cb + 0] = tf32(b1.x); Bs[buf][kb + 8][cb + 1] = tf32(b1.y);
        Bs[buf][kb + 8][cb + 2] = tf32(b1.z); Bs[buf][kb + 8][cb + 3] = tf32(b1.w);
    };
    auto comp = [&](int buf) {
        #pragma unroll
        for (int k0 = 0; k0 < 16; k0 += 8) {
            unsigned af[4][4], bf[4][2];
            #pragma unroll
            for (int mi = 0; mi < 4; mi++) {
                int m0 = wm + mi * 16 + gi;
                af[mi][0] = As[buf][k0 + tg][m0];
                af[mi][1] = As[buf][k0 + tg][m0 + 8];
                af[mi][2] = As[buf][k0 + 4 + tg][m0];
                af[mi][3] = As[buf][k0 + 4 + tg][m0 + 8];
            }
            #pragma unroll
            for (int ni = 0; ni < 4; ni++) {
                int n0 = wn + ni * 8 + gi;
                bf[ni][0] = Bs[buf][k0 + tg][n0];
                bf[ni][1] = Bs[buf][k0 + 4 + tg][n0];
            }
            #pragma unroll
            for (int mi = 0; mi < 4; mi++)
                #pragma unroll
                for (int ni = 0; ni < 4; ni++)
                    mma_tf32(acc[mi][ni], af[mi], bf[ni]);
        }
    };

    ldglob(0);
    stsh(0);
    __syncthreads();
    int buf = 0;
    for (int kt = 16; kt < K; kt += 16) {
        ldglob(kt);
        comp(buf);
        stsh(buf ^ 1);
        __syncthreads();
        buf ^= 1;
    }
    comp(buf);

    #pragma unroll
    for (int mi = 0; mi < 4; mi++) {
        int r0 = rowBase + wm + mi * 16 + gi;
        int r1 = r0 + 8;
        #pragma unroll
        for (int ni = 0; ni < 4; ni++) {
            int c = colBase + wn + ni * 8 + 2 * tg;
            float2 bv = *(const float2*)(bias + c);
            if (r0 < M) {
                float2 o = make_float2(acc[mi][ni][0] + bv.x, acc[mi][ni][1] + bv.y);
                *(float2*)&Cmat[(size_t)r0 * ldc + c] = o;
            }
            if (r1 < M) {
                float2 o = make_float2(acc[mi][ni][2] + bv.x, acc[mi][ni][3] + bv.y);
                *(float2*)&Cmat[(size_t)r1 * ldc + c] = o;
            }
        }
    }
}

// ------------------------- P[n,f] = sum_c Q[n,c] * We[f,c] -------------------
template <int C>
__global__ __launch_bounds__(256) void qe_k(
    const float* __restrict__ Q, int ld, const float* __restrict__ WeT,
    float* __restrict__ P, int n)
{
    __shared__ float WT[C * 16];
    for (int i = threadIdx.x; i < C * 16; i += 256) WT[i] = WeT[i];
    __syncthreads();

    int idx = blockIdx.x * 256 + threadIdx.x;
    int node = idx >> 4, f = idx & 15;
    if (node >= n) return;
    const float* q = Q + (size_t)node * ld;
    float acc = 0.f;
    #pragma unroll 8
    for (int c = 0; c < C; c++) acc += q[c] * WT[c * 16 + f];
    P[(size_t)node * 16 + f] = acc;
}

// ------------------------- fused attention (warp per dst node) ---------------
template <int C, bool RELU>
__global__ __launch_bounds__(256) void fused_attn_k(
    float* __restrict__ QKVS, int ld,
    const float* __restrict__ attrS, const int* __restrict__ srcS,
    const int* __restrict__ off, const float* __restrict__ P,
    const float* __restrict__ We, float isc, int n)
{
    constexpr int NV = C / 128;
    __shared__ float Ws[16 * C];
    for (int i = threadIdx.x; i < 16 * C; i += 256) Ws[i] = We[i];
    __syncthreads();

    const int node = blockIdx.x * 8 + (threadIdx.x >> 5);
    const int lane = threadIdx.x & 31;
    if (node >= n) return;

    const int e0 = off[node], e1 = off[node + 1];

    float4 q[NV];
    const float4* qb = (const float4*)(QKVS + (size_t)node * ld);
    #pragma unroll
    for (int i = 0; i < NV; i++) q[i] = qb[lane + i * 32];

    const float pP = (lane < 16) ? P[(size_t)node * 16 + lane] : 0.f;

    float m = -INFINITY, s = 0.f, tacc = 0.f;
    float4 vacc[NV];
    #pragma unroll
    for (int i = 0; i < NV; i++) vacc[i] = make_float4(0.f, 0.f, 0.f, 0.f);

    int sn_next = 0;
    float av_next = 0.f;
    if (e0 < e1) {
        sn_next = srcS[e0];
        av_next = (lane < 16) ? attrS[(size_t)e0 * 16 + lane] : 0.f;
    }

    for (int e = e0; e < e1; e++) {
        const int sn = sn_next;
        const float av = av_next;
        if (e + 1 < e1) {
            sn_next = srcS[e + 1];
            av_next = (lane < 16) ? attrS[(size_t)(e + 1) * 16 + lane] : 0.f;
        }

        const float4* kb = (const float4*)(QKVS + (size_t)sn * ld + C);
        const float4* vb = (const float4*)(QKVS + (size_t)sn * ld + 2 * C);
        float4 kv[NV], vv[NV];
        #pragma unroll
        for (int i = 0; i < NV; i++) { kv[i] = kb[lane + i * 32]; vv[i] = vb[lane + i * 32]; }

        float part = av * pP;
        #pragma unroll
        for (int i = 0; i < NV; i++)
            part += q[i].x * kv[i].x + q[i].y * kv[i].y
                  + q[i].z * kv[i].z + q[i].w * kv[i].w;
        #pragma unroll
        for (int o = 16; o; o >>= 1) part += __shfl_xor_sync(0xFFFFFFFFu, part, o);

        const float al = part * isc;
        const float mn = fmaxf(m, al);
        const float corr = __expf(m - mn);
        const float p = __expf(al - mn);
        m = mn;
        s = s * corr + p;
        tacc = tacc * corr + p * av;
        #pragma unroll
        for (int i = 0; i < NV; i++) {
            vacc[i].x = vacc[i].x * corr + p * vv[i].x;
            vacc[i].y = vacc[i].y * corr + p * vv[i].y;
            vacc[i].z = vacc[i].z * corr + p * vv[i].z;
            vacc[i].w = vacc[i].w * corr + p * vv[i].w;
        }
    }

    const float inv = 1.f / (s + 1e-16f);

    float4 ed[NV];
    #pragma unroll
    for (int i = 0; i < NV; i++) ed[i] = make_float4(0.f, 0.f, 0.f, 0.f);
    #pragma unroll
    for (int f = 0; f < 16; f++) {
        const float tf = __shfl_sync(0xFFFFFFFFu, tacc, f) * inv;
        #pragma unroll
        for (int i = 0; i < NV; i++) {
            float4 w = *(const float4*)&Ws[f * C + (lane + i * 32) * 4];
            ed[i].x += tf * w.x; ed[i].y += tf * w.y;
            ed[i].z += tf * w.z; ed[i].w += tf * w.w;
        }
    }

    float4* hb = (float4*)(QKVS + (size_t)node * ld + 3 * C);
    #pragma unroll
    for (int i = 0; i < NV; i++) {
        float4 sk = hb[lane + i * 32];
        float4 o;
        o.x = sk.x + vacc[i].x * inv + ed[i].x;
        o.y = sk.y + vacc[i].y * inv + ed[i].y;
        o.z = sk.z + vacc[i].z * inv + ed[i].z;
        o.w = sk.w + vacc[i].w * inv + ed[i].w;
        if (RELU) {
            o.x = fmaxf(o.x, 0.f); o.y = fmaxf(o.y, 0.f);
            o.z = fmaxf(o.z, 0.f); o.w = fmaxf(o.w, 0.f);
        }
        hb[lane + i * 32] = o;
    }
}

// ------------------------- classifier ----------------------------------------
__global__ __launch_bounds__(256) void classifier_k(
    const float* __restrict__ H, int ldh, const float* __restrict__ Wc,
    const float* __restrict__ bc, float* __restrict__ out, int M)
{
    __shared__ float Ws[256 * 10];
    for (int i = threadIdx.x; i < 2560; i += blockDim.x) Ws[i] = Wc[i];
    __syncthreads();

    int row  = blockIdx.x * 8 + (threadIdx.x >> 5);
    int lane = threadIdx.x & 31;
    if (row >= M) return;

    float acc[10];
    #pragma unroll
    for (int c = 0; c < 10; c++) acc[c] = 0.f;

    for (int k = lane; k < 256; k += 32) {
        float h = H[(size_t)row * ldh + k];
        #pragma unroll
        for (int c = 0; c < 10; c++) acc[c] += h * Ws[k * 10 + c];
    }
    #pragma unroll
    for (int c = 0; c < 10; c++)
        #pragma unroll
        for (int o = 16; o; o >>= 1)
            acc[c] += __shfl_xor_sync(0xFFFFFFFFu, acc[c], o);

    if (lane == 0) {
        #pragma unroll
        for (int c = 0; c < 10; c++)
            out[(size_t)row * 10 + c] = acc[c] + bc[c];
    }
}

// ------------------------- launch --------------------------------------------
extern "C" void kernel_launch(void* const* d_in, const int* in_sizes, int n_in,
                              void* d_out, int out_size)
{
    const float* x    = (const float*)d_in[0];
    const int*   ei   = (const int*)d_in[1];
    const float* attr = (const float*)d_in[2];
    const int* src = ei;
    const int* dst = ei + NE;

    float *B1, *B2, *P, *Wp, *bp, *WeT, *attrS;
    int *cnt, *off, *bsum, *cursor, *srcS;
    cudaGetSymbolAddress((void**)&B1,     g_B1);
    cudaGetSymbolAddress((void**)&B2,     g_B2);
    cudaGetSymbolAddress((void**)&P,      g_P);
    cudaGetSymbolAddress((void**)&Wp,     g_Wp);
    cudaGetSymbolAddress((void**)&bp,     g_bp);
    cudaGetSymbolAddress((void**)&WeT,    g_WeT);
    cudaGetSymbolAddress((void**)&cnt,    g_cnt);
    cudaGetSymbolAddress((void**)&off,    g_off);
    cudaGetSymbolAddress((void**)&bsum,   g_bsum);
    cudaGetSymbolAddress((void**)&cursor, g_cursor);
    cudaGetSymbolAddress((void**)&srcS,   g_srcS);
    cudaGetSymbolAddress((void**)&attrS,  g_attrS);

    auto IN = [&](int i) { return (const float*)d_in[i]; };

    // ---- sort edges by dst (once; reused by all 3 layers) ----
    zero_cnt_k<<<(NN + 255) / 256, 256>>>(cnt, NN);
    hist_k<<<(NE + 255) / 256, 256>>>(dst, cnt, NE);
    scan1_k<<<SCAN_NB, SCAN_T>>>(cnt, off, bsum, NN);
    scan2_k<<<1, 128>>>(bsum, SCAN_NB);
    scan3_k<<<SCAN_NB, SCAN_T>>>(off, bsum, cursor, NN, NE);
    scatter_k<<<(NE + 255) / 256, 256>>>(src, dst, attr, cursor, srcS, attrS, NE);

    // ---- layers ----
    const float* Ain[3]  = { x, B1 + 3 * 128, B2 + 3 * 128 };
    int          lda[3]  = { 128, 512, 512 };
    int          din[3]  = { 128, 128, 128 };
    int          Cc[3]   = { 128, 128, 256 };
    float*       outb[3] = { B1, B2, B1 };
    int          ldo[3]  = { 512, 512, 1024 };

    for (int l = 0; l < 3; l++) {
        const int base = 3 + l * 9;
        const float *Wq = IN(base + 0), *bq = IN(base + 1);
        const float *Wk = IN(base + 2), *bk = IN(base + 3);
        const float *Wv = IN(base + 4), *bv = IN(base + 5);
        const float *We = IN(base + 6);
        const float *Wr = IN(base + 7), *br = IN(base + 8);
        const int C = Cc[l];
        float* out = outb[l];
        const int ld = ldo[l];

        pack_k<<<256, 256>>>(Wq, Wk, Wv, Wr, bq, bk, bv, br, We,
                             Wp, bp, WeT, din[l], C);

        dim3 gg((NN + 127) / 128, 4 * C / 128);
        sgemm_tc_k<<<gg, 256>>>(Ain[l], lda[l], Wp, 4 * C, bp, out, ld, NN, din[l]);

        if (C == 128) qe_k<128><<<(NN * 16 + 255) / 256, 256>>>(out, ld, WeT, P, NN);
        else          qe_k<256><<<(NN * 16 + 255) / 256, 256>>>(out, ld, WeT, P, NN);

        float isc = 1.0f / sqrtf((float)C);
        if (C == 128) {
            if (l < 2)
                fused_attn_k<128, true ><<<(NN + 7) / 8, 256>>>(out, ld, attrS, srcS, off, P, We, isc, NN);
            else
                fused_attn_k<128, false><<<(NN + 7) / 8, 256>>>(out, ld, attrS, srcS, off, P, We, isc, NN);
        } else {
            if (l < 2)
                fused_attn_k<256, true ><<<(NN + 7) / 8, 256>>>(out, ld, attrS, srcS, off, P, We, isc, NN);
            else
                fused_attn_k<256, false><<<(NN + 7) / 8, 256>>>(out, ld, attrS, srcS, off, P, We, isc, NN);
        }
    }

    classifier_k<<<(NN + 7) / 8, 256>>>(B1 + 768, 1024, IN(30), IN(31), (float*)d_out, NN);
}

// round 6
// speedup vs baseline: 2.6147x; 1.0118x over previous
#include <cuda_runtime.h>
#include <math.h>

#define NN 100000
#define NE 800000
#define SCAN_T 1024
#define SCAN_NB ((NN + SCAN_T - 1) / SCAN_T)

// ------------------------- scratch (static device globals) -------------------
__device__ float g_B1[(size_t)NN * 1024];
__device__ float g_B2[(size_t)NN * 512];
__device__ float g_P[(size_t)NN * 16];
__device__ float g_Wp[256 * 1024];
__device__ float g_bp[1024];
__device__ float g_WeT[256 * 16];
__device__ int   g_cnt[NN];
__device__ int   g_off[NN + 1];
__device__ int   g_bsum[SCAN_NB + 1];
__device__ int   g_cursor[NN];
__device__ int   g_srcS[NE];
__device__ float g_attrS[(size_t)NE * 16];

// ------------------------- helpers ------------------------------------------
__device__ __forceinline__ unsigned tf32(float x) {
    unsigned u;
    asm("cvt.rna.tf32.f32 %0, %1;" : "=r"(u) : "f"(x));
    return u;
}

__device__ __forceinline__ void mma_tf32(float* c, const unsigned* a, const unsigned* b) {
    asm volatile(
        "mma.sync.aligned.m16n8k8.row.col.f32.tf32.tf32.f32 "
        "{%0,%1,%2,%3}, {%4,%5,%6,%7}, {%8,%9}, {%0,%1,%2,%3};"
        : "+f"(c[0]), "+f"(c[1]), "+f"(c[2]), "+f"(c[3])
        : "r"(a[0]), "r"(a[1]), "r"(a[2]), "r"(a[3]), "r"(b[0]), "r"(b[1]));
}

// ------------------------- weight packer -------------------------------------
__global__ void pack_k(const float* __restrict__ Wq, const float* __restrict__ Wk,
                       const float* __restrict__ Wv, const float* __restrict__ Ws,
                       const float* __restrict__ bq, const float* __restrict__ bk,
                       const float* __restrict__ bv, const float* __restrict__ bs,
                       const float* __restrict__ We,
                       float* __restrict__ Wp, float* __restrict__ bp,
                       float* __restrict__ WeT, int din, int C)
{
    int N4 = 4 * C;
    int total = din * N4;
    for (int idx = blockIdx.x * blockDim.x + threadIdx.x; idx < total;
         idx += gridDim.x * blockDim.x) {
        int k = idx / N4, j = idx - k * N4;
        int sel = j / C, c = j - sel * C;
        const float* W = sel == 0 ? Wq : sel == 1 ? Wk : sel == 2 ? Wv : Ws;
        Wp[idx] = W[k * C + c];
        if (k == 0) {
            const float* bb = sel == 0 ? bq : sel == 1 ? bk : sel == 2 ? bv : bs;
            bp[j] = bb[c];
        }
        if (idx < 16 * C) {
            int f = idx / C, cc = idx - f * C;
            WeT[cc * 16 + f] = We[idx];
        }
    }
}

// ------------------------- sort: histogram / scan / scatter ------------------
__global__ void zero_cnt_k(int* __restrict__ cnt, int n)
{
    int i = blockIdx.x * blockDim.x + threadIdx.x;
    if (i < n) cnt[i] = 0;
}

__global__ void hist_k(const int* __restrict__ dst, int* __restrict__ cnt, int nE)
{
    int e = blockIdx.x * blockDim.x + threadIdx.x;
    if (e < nE) atomicAdd(&cnt[dst[e]], 1);
}

__global__ void scan1_k(const int* __restrict__ cnt, int* __restrict__ off,
                        int* __restrict__ bsum, int n)
{
    __shared__ int s[SCAN_T];
    int gid = blockIdx.x * SCAN_T + threadIdx.x;
    int v = (gid < n) ? cnt[gid] : 0;
    s[threadIdx.x] = v;
    __syncthreads();
    for (int d = 1; d < SCAN_T; d <<= 1) {
        int t = (threadIdx.x >= d) ? s[threadIdx.x - d] : 0;
        __syncthreads();
        s[threadIdx.x] += t;
        __syncthreads();
    }
    if (gid < n) off[gid] = s[threadIdx.x] - v;
    if (threadIdx.x == SCAN_T - 1) bsum[blockIdx.x] = s[threadIdx.x];
}

__global__ void scan2_k(int* __restrict__ bsum, int nb)
{
    __shared__ int s[128];
    int v = (threadIdx.x < nb) ? bsum[threadIdx.x] : 0;
    s[threadIdx.x] = v;
    __syncthreads();
    for (int d = 1; d < 128; d <<= 1) {
        int t = (threadIdx.x >= d) ? s[threadIdx.x - d] : 0;
        __syncthreads();
        s[threadIdx.x] += t;
        __syncthreads();
    }
    if (threadIdx.x < nb) bsum[threadIdx.x] = s[threadIdx.x] - v;
}

__global__ void scan3_k(int* __restrict__ off, const int* __restrict__ bsum,
                        int* __restrict__ cursor, int n, int total)
{
    int gid = blockIdx.x * SCAN_T + threadIdx.x;
    if (gid < n) {
        int o = off[gid] + bsum[blockIdx.x];
        off[gid] = o;
        cursor[gid] = o;
    }
    if (gid == 0) off[n] = total;
}

__global__ void scatter_k(const int* __restrict__ src, const int* __restrict__ dst,
                          const float* __restrict__ attr, int* __restrict__ cursor,
                          int* __restrict__ srcS, float* __restrict__ attrS, int nE)
{
    int e = blockIdx.x * blockDim.x + threadIdx.x;
    if (e >= nE) return;
    int pos = atomicAdd(&cursor[dst[e]], 1);
    srcS[pos] = src[e];
    const float4* a4 = (const float4*)(attr + (size_t)e * 16);
    float4* o4 = (float4*)(attrS + (size_t)pos * 16);
    o4[0] = a4[0]; o4[1] = a4[1]; o4[2] = a4[2]; o4[3] = a4[3];
}

// ------------------------- TF32 tensor-core GEMM -----------------------------
__global__ __launch_bounds__(256, 2) void sgemm_tc_k(
    const float* __restrict__ A, int lda,
    const float* __restrict__ B, int ldb,
    const float* __restrict__ bias,
    float* __restrict__ Cmat, int ldc,
    int M, int K)
{
    __shared__ unsigned As[2][16][136];
    __shared__ unsigned Bs[2][16][136];

    const int t    = threadIdx.x;
    const int wid  = t >> 5;
    const int lane = t & 31;
    const int tg   = lane & 3;
    const int gi   = lane >> 2;
    const int wm   = (wid >> 2) * 64;
    const int wn   = (wid & 3) * 32;
    const int rowBase = blockIdx.x * 128;
    const int colBase = blockIdx.y * 128;

    const int ar = t >> 2;
    const int kc = (t & 3) * 4;
    const int kb = t >> 5;
    const int cb = (t & 31) * 4;

    float acc[4][4][4];
    #pragma unroll
    for (int mi = 0; mi < 4; mi++)
        #pragma unroll
        for (int ni = 0; ni < 4; ni++)
            #pragma unroll
            for (int c = 0; c < 4; c++) acc[mi][ni][c] = 0.f;

    const float4 z4 = make_float4(0.f, 0.f, 0.f, 0.f);
    float4 a0, a1, b0, b1;

    auto ldglob = [&](int kt) {
        int r0 = rowBase + ar, r1 = r0 + 64;
        a0 = (r0 < M) ? *(const float4*)(A + (size_t)r0 * lda + kt + kc) : z4;
        a1 = (r1 < M) ? *(const float4*)(A + (size_t)r1 * lda + kt + kc) : z4;
        b0 = *(const float4*)(B + (size_t)(kt + kb) * ldb + colBase + cb);
        b1 = *(const float4*)(B + (size_t)(kt + kb + 8) * ldb + colBase + cb);
    };
    auto stsh = [&](int buf) {
        As[buf][kc + 0][ar] = tf32(a0.x); As[buf][kc + 1][ar] = tf32(a0.y);
        As[buf][kc + 2][ar] = tf32(a0.z); As[buf][kc + 3][ar] = tf32(a0.w);
        As[buf][kc + 0][ar + 64] = tf32(a1.x); As[buf][kc + 1][ar + 64] = tf32(a1.y);
        As[buf][kc + 2][ar + 64] = tf32(a1.z); As[buf][kc + 3][ar + 64] = tf32(a1.w);
        Bs[buf][kb][cb + 0] = tf32(b0.x); Bs[buf][kb][cb + 1] = tf32(b0.y);
        Bs[buf][kb][cb + 2] = tf32(b0.z); Bs[buf][kb][cb + 3] = tf32(b0.w);
        Bs[buf][kb + 8][cb + 0] = tf32(b1.x); Bs[buf][kb + 8][cb + 1] = tf32(b1.y);
        Bs[buf][kb + 8][cb + 2] = tf32(b1.z); Bs[buf][kb + 8][cb + 3] = tf32(b1.w);
    };
    auto comp = [&](int buf) {
        #pragma unroll
        for (int k0 = 0; k0 < 16; k0 += 8) {
            unsigned af[4][4], bf[4][2];
            #pragma unroll
            for (int mi = 0; mi < 4; mi++) {
                int m0 = wm + mi * 16 + gi;
                af[mi][0] = As[buf][k0 + tg][m0];
                af[mi][1] = As[buf][k0 + tg][m0 + 8];
                af[mi][2] = As[buf][k0 + 4 + tg][m0];
                af[mi][3] = As[buf][k0 + 4 + tg][m0 + 8];
            }
            #pragma unroll
            for (int ni = 0; ni < 4; ni++) {
                int n0 = wn + ni * 8 + gi;
                bf[ni][0] = Bs[buf][k0 + tg][n0];
                bf[ni][1] = Bs[buf][k0 + 4 + tg][n0];
            }
            #pragma unroll
            for (int mi = 0; mi < 4; mi++)
                #pragma unroll
                for (int ni = 0; ni < 4; ni++)
                    mma_tf32(acc[mi][ni], af[mi], bf[ni]);
        }
    };

    ldglob(0);
    stsh(0);
    __syncthreads();
    int buf = 0;
    for (int kt = 16; kt < K; kt += 16) {
        ldglob(kt);
        comp(buf);
        stsh(buf ^ 1);
        __syncthreads();
        buf ^= 1;
    }
    comp(buf);

    #pragma unroll
    for (int mi = 0; mi < 4; mi++) {
        int r0 = rowBase + wm + mi * 16 + gi;
        int r1 = r0 + 8;
        #pragma unroll
        for (int ni = 0; ni < 4; ni++) {
            int c = colBase + wn + ni * 8 + 2 * tg;
            float2 bv = *(const float2*)(bias + c);
            if (r0 < M) {
                float2 o = make_float2(acc[mi][ni][0] + bv.x, acc[mi][ni][1] + bv.y);
                *(float2*)&Cmat[(size_t)r0 * ldc + c] = o;
            }
            if (r1 < M) {
                float2 o = make_float2(acc[mi][ni][2] + bv.x, acc[mi][ni][3] + bv.y);
                *(float2*)&Cmat[(size_t)r1 * ldc + c] = o;
            }
        }
    }
}

// ------------------------- P[n,f] = sum_c Q[n,c] * We[f,c] -------------------
template <int C>
__global__ __launch_bounds__(256) void qe_k(
    const float* __restrict__ Q, int ld, const float* __restrict__ WeT,
    float* __restrict__ P, int n)
{
    __shared__ float WT[C * 16];
    for (int i = threadIdx.x; i < C * 16; i += 256) WT[i] = WeT[i];
    __syncthreads();

    int idx = blockIdx.x * 256 + threadIdx.x;
    int node = idx >> 4, f = idx & 15;
    if (node >= n) return;
    const float* q = Q + (size_t)node * ld;
    float acc = 0.f;
    #pragma unroll 8
    for (int c = 0; c < C; c++) acc += q[c] * WT[c * 16 + f];
    P[(size_t)node * 16 + f] = acc;
}

// ------------------------- fused attention (warp per dst, 2-edge pipeline) ---
template <int C, bool RELU>
__global__ __launch_bounds__(256) void fused_attn_k(
    float* __restrict__ QKVS, int ld,
    const float* __restrict__ attrS, const int* __restrict__ srcS,
    const int* __restrict__ off, const float* __restrict__ P,
    const float* __restrict__ We, float isc, int n)
{
    constexpr int NV = C / 128;
    __shared__ float Ws[16 * C];
    for (int i = threadIdx.x; i < 16 * C; i += 256) Ws[i] = We[i];
    __syncthreads();

    const int node = blockIdx.x * 8 + (threadIdx.x >> 5);
    const int lane = threadIdx.x & 31;
    if (node >= n) return;

    const int e0 = off[node], e1 = off[node + 1];

    float4 q[NV];
    const float4* qb = (const float4*)(QKVS + (size_t)node * ld);
    #pragma unroll
    for (int i = 0; i < NV; i++) q[i] = qb[lane + i * 32];

    const float pP = (lane < 16) ? P[(size_t)node * 16 + lane] : 0.f;

    float m = -INFINITY, s = 0.f, tacc = 0.f;
    float4 vacc[NV];
    #pragma unroll
    for (int i = 0; i < NV; i++) vacc[i] = make_float4(0.f, 0.f, 0.f, 0.f);

    // prefetch first pair of indices / attrs
    int pf_sn0 = 0, pf_sn1 = 0;
    float pf_av0 = 0.f, pf_av1 = 0.f;
    if (e0 < e1) {
        pf_sn0 = srcS[e0];
        pf_av0 = (lane < 16) ? attrS[(size_t)e0 * 16 + lane] : 0.f;
    }
    if (e0 + 1 < e1) {
        pf_sn1 = srcS[e0 + 1];
        pf_av1 = (lane < 16) ? attrS[(size_t)(e0 + 1) * 16 + lane] : 0.f;
    }

    int e = e0;
    while (e + 1 < e1) {
        const int sn0 = pf_sn0, sn1 = pf_sn1;
        const float av0 = pf_av0, av1 = pf_av1;
        if (e + 2 < e1) {
            pf_sn0 = srcS[e + 2];
            pf_av0 = (lane < 16) ? attrS[(size_t)(e + 2) * 16 + lane] : 0.f;
        }
        if (e + 3 < e1) {
            pf_sn1 = srcS[e + 3];
            pf_av1 = (lane < 16) ? attrS[(size_t)(e + 3) * 16 + lane] : 0.f;
        }

        const float4* kb0 = (const float4*)(QKVS + (size_t)sn0 * ld + C);
        const float4* vb0 = (const float4*)(QKVS + (size_t)sn0 * ld + 2 * C);
        const float4* kb1 = (const float4*)(QKVS + (size_t)sn1 * ld + C);
        const float4* vb1 = (const float4*)(QKVS + (size_t)sn1 * ld + 2 * C);

        float4 kv0[NV], vv0[NV], kv1[NV], vv1[NV];
        #pragma unroll
        for (int i = 0; i < NV; i++) {
            kv0[i] = kb0[lane + i * 32]; vv0[i] = vb0[lane + i * 32];
            kv1[i] = kb1[lane + i * 32]; vv1[i] = vb1[lane + i * 32];
        }

        float p0 = av0 * pP, p1 = av1 * pP;
        #pragma unroll
        for (int i = 0; i < NV; i++) {
            p0 += q[i].x * kv0[i].x + q[i].y * kv0[i].y
                + q[i].z * kv0[i].z + q[i].w * kv0[i].w;
            p1 += q[i].x * kv1[i].x + q[i].y * kv1[i].y
                + q[i].z * kv1[i].z + q[i].w * kv1[i].w;
        }
        // two independent butterfly reduces, interleaved by the compiler
        #pragma unroll
        for (int o = 16; o; o >>= 1) {
            p0 += __shfl_xor_sync(0xFFFFFFFFu, p0, o);
            p1 += __shfl_xor_sync(0xFFFFFFFFu, p1, o);
        }

        const float al0 = p0 * isc, al1 = p1 * isc;
        const float mn = fmaxf(m, fmaxf(al0, al1));
        const float corr = __expf(m - mn);
        const float w0 = __expf(al0 - mn);
        const float w1 = __expf(al1 - mn);
        m = mn;
        s = s * corr + w0 + w1;
        tacc = tacc * corr + w0 * av0 + w1 * av1;
        #pragma unroll
        for (int i = 0; i < NV; i++) {
            vacc[i].x = vacc[i].x * corr + w0 * vv0[i].x + w1 * vv1[i].x;
            vacc[i].y = vacc[i].y * corr + w0 * vv0[i].y + w1 * vv1[i].y;
            vacc[i].z = vacc[i].z * corr + w0 * vv0[i].z + w1 * vv1[i].z;
            vacc[i].w = vacc[i].w * corr + w0 * vv0[i].w + w1 * vv1[i].w;
        }
        e += 2;
    }

    if (e < e1) {   // odd tail (indices already prefetched into slot 0)
        const int sn = pf_sn0;
        const float av = pf_av0;
        const float4* kb = (const float4*)(QKVS + (size_t)sn * ld + C);
        const float4* vb = (const float4*)(QKVS + (size_t)sn * ld + 2 * C);
        float4 kv[NV], vv[NV];
        #pragma unroll
        for (int i = 0; i < NV; i++) { kv[i] = kb[lane + i * 32]; vv[i] = vb[lane + i * 32]; }

        float part = av * pP;
        #pragma unroll
        for (int i = 0; i < NV; i++)
            part += q[i].x * kv[i].x + q[i].y * kv[i].y
                  + q[i].z * kv[i].z + q[i].w * kv[i].w;
        #pragma unroll
        for (int o = 16; o; o >>= 1) part += __shfl_xor_sync(0xFFFFFFFFu, part, o);

        const float al = part * isc;
        const float mn = fmaxf(m, al);
        const float corr = __expf(m - mn);
        const float p = __expf(al - mn);
        m = mn;
        s = s * corr + p;
        tacc = tacc * corr + p * av;
        #pragma unroll
        for (int i = 0; i < NV; i++) {
            vacc[i].x = vacc[i].x * corr + p * vv[i].x;
            vacc[i].y = vacc[i].y * corr + p * vv[i].y;
            vacc[i].z = vacc[i].z * corr + p * vv[i].z;
            vacc[i].w = vacc[i].w * corr + p * vv[i].w;
        }
    }

    const float inv = 1.f / (s + 1e-16f);

    float4 ed[NV];
    #pragma unroll
    for (int i = 0; i < NV; i++) ed[i] = make_float4(0.f, 0.f, 0.f, 0.f);
    #pragma unroll
    for (int f = 0; f < 16; f++) {
        const float tf = __shfl_sync(0xFFFFFFFFu, tacc, f) * inv;
        #pragma unroll
        for (int i = 0; i < NV; i++) {
            float4 w = *(const float4*)&Ws[f * C + (lane + i * 32) * 4];
            ed[i].x += tf * w.x; ed[i].y += tf * w.y;
            ed[i].z += tf * w.z; ed[i].w += tf * w.w;
        }
    }

    float4* hb = (float4*)(QKVS + (size_t)node * ld + 3 * C);
    #pragma unroll
    for (int i = 0; i < NV; i++) {
        float4 sk = hb[lane + i * 32];
        float4 o;
        o.x = sk.x + vacc[i].x * inv + ed[i].x;
        o.y = sk.y + vacc[i].y * inv + ed[i].y;
        o.z = sk.z + vacc[i].z * inv + ed[i].z;
        o.w = sk.w + vacc[i].w * inv + ed[i].w;
        if (RELU) {
            o.x = fmaxf(o.x, 0.f); o.y = fmaxf(o.y, 0.f);
            o.z = fmaxf(o.z, 0.f); o.w = fmaxf(o.w, 0.f);
        }
        hb[lane + i * 32] = o;
    }
}

// ------------------------- classifier ----------------------------------------
__global__ __launch_bounds__(256) void classifier_k(
    const float* __restrict__ H, int ldh, const float* __restrict__ Wc,
    const float* __restrict__ bc, float* __restrict__ out, int M)
{
    __shared__ float Ws[256 * 10];
    for (int i = threadIdx.x; i < 2560; i += blockDim.x) Ws[i] = Wc[i];
    __syncthreads();

    int row  = blockIdx.x * 8 + (threadIdx.x >> 5);
    int lane = threadIdx.x & 31;
    if (row >= M) return;

    float acc[10];
    #pragma unroll
    for (int c = 0; c < 10; c++) acc[c] = 0.f;

    for (int k = lane; k < 256; k += 32) {
        float h = H[(size_t)row * ldh + k];
        #pragma unroll
        for (int c = 0; c < 10; c++) acc[c] += h * Ws[k * 10 + c];
    }
    #pragma unroll
    for (int c = 0; c < 10; c++)
        #pragma unroll
        for (int o = 16; o; o >>= 1)
            acc[c] += __shfl_xor_sync(0xFFFFFFFFu, acc[c], o);

    if (lane == 0) {
        #pragma unroll
        for (int c = 0; c < 10; c++)
            out[(size_t)row * 10 + c] = acc[c] + bc[c];
    }
}

// ------------------------- launch --------------------------------------------
extern "C" void kernel_launch(void* const* d_in, const int* in_sizes, int n_in,
                              void* d_out, int out_size)
{
    const float* x    = (const float*)d_in[0];
    const int*   ei   = (const int*)d_in[1];
    const float* attr = (const float*)d_in[2];
    const int* src = ei;
    const int* dst = ei + NE;

    float *B1, *B2, *P, *Wp, *bp, *WeT, *attrS;
    int *cnt, *off, *bsum, *cursor, *srcS;
    cudaGetSymbolAddress((void**)&B1,     g_B1);
    cudaGetSymbolAddress((void**)&B2,     g_B2);
    cudaGetSymbolAddress((void**)&P,      g_P);
    cudaGetSymbolAddress((void**)&Wp,     g_Wp);
    cudaGetSymbolAddress((void**)&bp,     g_bp);
    cudaGetSymbolAddress((void**)&WeT,    g_WeT);
    cudaGetSymbolAddress((void**)&cnt,    g_cnt);
    cudaGetSymbolAddress((void**)&off,    g_off);
    cudaGetSymbolAddress((void**)&bsum,   g_bsum);
    cudaGetSymbolAddress((void**)&cursor, g_cursor);
    cudaGetSymbolAddress((void**)&srcS,   g_srcS);
    cudaGetSymbolAddress((void**)&attrS,  g_attrS);

    auto IN = [&](int i) { return (const float*)d_in[i]; };

    // ---- sort edges by dst (once; reused by all 3 layers) ----
    zero_cnt_k<<<(NN + 255) / 256, 256>>>(cnt, NN);
    hist_k<<<(NE + 255) / 256, 256>>>(dst, cnt, NE);
    scan1_k<<<SCAN_NB, SCAN_T>>>(cnt, off, bsum, NN);
    scan2_k<<<1, 128>>>(bsum, SCAN_NB);
    scan3_k<<<SCAN_NB, SCAN_T>>>(off, bsum, cursor, NN, NE);
    scatter_k<<<(NE + 255) / 256, 256>>>(src, dst, attr, cursor, srcS, attrS, NE);

    // ---- layers ----
    const float* Ain[3]  = { x, B1 + 3 * 128, B2 + 3 * 128 };
    int          lda[3]  = { 128, 512, 512 };
    int          din[3]  = { 128, 128, 128 };
    int          Cc[3]   = { 128, 128, 256 };
    float*       outb[3] = { B1, B2, B1 };
    int          ldo[3]  = { 512, 512, 1024 };

    for (int l = 0; l < 3; l++) {
        const int base = 3 + l * 9;
        const float *Wq = IN(base + 0), *bq = IN(base + 1);
        const float *Wk = IN(base + 2), *bk = IN(base + 3);
        const float *Wv = IN(base + 4), *bv = IN(base + 5);
        const float *We = IN(base + 6);
        const float *Wr = IN(base + 7), *br = IN(base + 8);
        const int C = Cc[l];
        float* out = outb[l];
        const int ld = ldo[l];

        pack_k<<<256, 256>>>(Wq, Wk, Wv, Wr, bq, bk, bv, br, We,
                             Wp, bp, WeT, din[l], C);

        dim3 gg((NN + 127) / 128, 4 * C / 128);
        sgemm_tc_k<<<gg, 256>>>(Ain[l], lda[l], Wp, 4 * C, bp, out, ld, NN, din[l]);

        if (C == 128) qe_k<128><<<(NN * 16 + 255) / 256, 256>>>(out, ld, WeT, P, NN);
        else          qe_k<256><<<(NN * 16 + 255) / 256, 256>>>(out, ld, WeT, P, NN);

        float isc = 1.0f / sqrtf((float)C);
        if (C == 128) {
            if (l < 2)
                fused_attn_k<128, true ><<<(NN + 7) / 8, 256>>>(out, ld, attrS, srcS, off, P, We, isc, NN);
            else
                fused_attn_k<128, false><<<(NN + 7) / 8, 256>>>(out, ld, attrS, srcS, off, P, We, isc, NN);
        } else {
            if (l < 2)
                fused_attn_k<256, true ><<<(NN + 7) / 8, 256>>>(out, ld, attrS, srcS, off, P, We, isc, NN);
            else
                fused_attn_k<256, false><<<(NN + 7) / 8, 256>>>(out, ld, attrS, srcS, off, P, We, isc, NN);
        }
    }

    classifier_k<<<(NN + 7) / 8, 256>>>(B1 + 768, 1024, IN(30), IN(31), (float*)d_out, NN);
}

// round 7
// speedup vs baseline: 2.9218x; 1.1175x over previous
#include <cuda_runtime.h>
#include <cuda_fp16.h>
#include <math.h>

#define NN 100000
#define NE 800000
#define SCAN_T 1024
#define SCAN_NB ((NN + SCAN_T - 1) / SCAN_T)

// ------------------------- scratch (static device globals) -------------------
__device__ float  g_B1[(size_t)NN * 1024];
__device__ float  g_B2[(size_t)NN * 512];
__device__ __half g_KV[(size_t)NN * 512];    // compact fp16 k|v per node (2C halfs)
__device__ float  g_P[(size_t)NN * 16];
__device__ float  g_Wp[256 * 1024];
__device__ float  g_bp[1024];
__device__ float  g_WeT[256 * 16];
__device__ int    g_cnt[NN];
__device__ int    g_off[NN + 1];
__device__ int    g_bsum[SCAN_NB + 1];
__device__ int    g_cursor[NN];
__device__ int    g_srcS[NE];
__device__ float  g_attrS[(size_t)NE * 16];

// ------------------------- helpers ------------------------------------------
__device__ __forceinline__ unsigned tf32(float x) {
    unsigned u;
    asm("cvt.rna.tf32.f32 %0, %1;" : "=r"(u) : "f"(x));
    return u;
}

__device__ __forceinline__ void mma_tf32(float* c, const unsigned* a, const unsigned* b) {
    asm volatile(
        "mma.sync.aligned.m16n8k8.row.col.f32.tf32.tf32.f32 "
        "{%0,%1,%2,%3}, {%4,%5,%6,%7}, {%8,%9}, {%0,%1,%2,%3};"
        : "+f"(c[0]), "+f"(c[1]), "+f"(c[2]), "+f"(c[3])
        : "r"(a[0]), "r"(a[1]), "r"(a[2]), "r"(a[3]), "r"(b[0]), "r"(b[1]));
}

// ------------------------- weight packer -------------------------------------
__global__ void pack_k(const float* __restrict__ Wq, const float* __restrict__ Wk,
                       const float* __restrict__ Wv, const float* __restrict__ Ws,
                       const float* __restrict__ bq, const float* __restrict__ bk,
                       const float* __restrict__ bv, const float* __restrict__ bs,
                       const float* __restrict__ We,
                       float* __restrict__ Wp, float* __restrict__ bp,
                       float* __restrict__ WeT, int din, int C)
{
    int N4 = 4 * C;
    int total = din * N4;
    for (int idx = blockIdx.x * blockDim.x + threadIdx.x; idx < total;
         idx += gridDim.x * blockDim.x) {
        int k = idx / N4, j = idx - k * N4;
        int sel = j / C, c = j - sel * C;
        const float* W = sel == 0 ? Wq : sel == 1 ? Wk : sel == 2 ? Wv : Ws;
        Wp[idx] = W[k * C + c];
        if (k == 0) {
            const float* bb = sel == 0 ? bq : sel == 1 ? bk : sel == 2 ? bv : bs;
            bp[j] = bb[c];
        }
        if (idx < 16 * C) {
            int f = idx / C, cc = idx - f * C;
            WeT[cc * 16 + f] = We[idx];
        }
    }
}

// ------------------------- sort: histogram / scan / scatter ------------------
__global__ void zero_cnt_k(int* __restrict__ cnt, int n)
{
    int i = blockIdx.x * blockDim.x + threadIdx.x;
    if (i < n) cnt[i] = 0;
}

__global__ void hist_k(const int* __restrict__ dst, int* __restrict__ cnt, int nE)
{
    int e = blockIdx.x * blockDim.x + threadIdx.x;
    if (e < nE) atomicAdd(&cnt[dst[e]], 1);
}

__global__ void scan1_k(const int* __restrict__ cnt, int* __restrict__ off,
                        int* __restrict__ bsum, int n)
{
    __shared__ int s[SCAN_T];
    int gid = blockIdx.x * SCAN_T + threadIdx.x;
    int v = (gid < n) ? cnt[gid] : 0;
    s[threadIdx.x] = v;
    __syncthreads();
    for (int d = 1; d < SCAN_T; d <<= 1) {
        int t = (threadIdx.x >= d) ? s[threadIdx.x - d] : 0;
        __syncthreads();
        s[threadIdx.x] += t;
        __syncthreads();
    }
    if (gid < n) off[gid] = s[threadIdx.x] - v;
    if (threadIdx.x == SCAN_T - 1) bsum[blockIdx.x] = s[threadIdx.x];
}

__global__ void scan2_k(int* __restrict__ bsum, int nb)
{
    __shared__ int s[128];
    int v = (threadIdx.x < nb) ? bsum[threadIdx.x] : 0;
    s[threadIdx.x] = v;
    __syncthreads();
    for (int d = 1; d < 128; d <<= 1) {
        int t = (threadIdx.x >= d) ? s[threadIdx.x - d] : 0;
        __syncthreads();
        s[threadIdx.x] += t;
        __syncthreads();
    }
    if (threadIdx.x < nb) bsum[threadIdx.x] = s[threadIdx.x] - v;
}

__global__ void scan3_k(int* __restrict__ off, const int* __restrict__ bsum,
                        int* __restrict__ cursor, int n, int total)
{
    int gid = blockIdx.x * SCAN_T + threadIdx.x;
    if (gid < n) {
        int o = off[gid] + bsum[blockIdx.x];
        off[gid] = o;
        cursor[gid] = o;
    }
    if (gid == 0) off[n] = total;
}

__global__ void scatter_k(const int* __restrict__ src, const int* __restrict__ dst,
                          const float* __restrict__ attr, int* __restrict__ cursor,
                          int* __restrict__ srcS, float* __restrict__ attrS, int nE)
{
    int e = blockIdx.x * blockDim.x + threadIdx.x;
    if (e >= nE) return;
    int pos = atomicAdd(&cursor[dst[e]], 1);
    srcS[pos] = src[e];
    const float4* a4 = (const float4*)(attr + (size_t)e * 16);
    float4* o4 = (float4*)(attrS + (size_t)pos * 16);
    o4[0] = a4[0]; o4[1] = a4[1]; o4[2] = a4[2]; o4[3] = a4[3];
}

// ------------------------- TF32 tensor-core GEMM -----------------------------
// Columns [Ckv, 3*Ckv) are emitted to the compact fp16 KV buffer instead of
// fp32 Cmat (k|v per row, 2*Ckv halfs).
__global__ __launch_bounds__(256, 2) void sgemm_tc_k(
    const float* __restrict__ A, int lda,
    const float* __restrict__ B, int ldb,
    const float* __restrict__ bias,
    float* __restrict__ Cmat, int ldc,
    __half* __restrict__ KV, int Ckv,
    int M, int K)
{
    __shared__ unsigned As[2][16][136];
    __shared__ unsigned Bs[2][16][136];

    const int t    = threadIdx.x;
    const int wid  = t >> 5;
    const int lane = t & 31;
    const int tg   = lane & 3;
    const int gi   = lane >> 2;
    const int wm   = (wid >> 2) * 64;
    const int wn   = (wid & 3) * 32;
    const int rowBase = blockIdx.x * 128;
    const int colBase = blockIdx.y * 128;

    const int ar = t >> 2;
    const int kc = (t & 3) * 4;
    const int kb = t >> 5;
    const int cb = (t & 31) * 4;

    float acc[4][4][4];
    #pragma unroll
    for (int mi = 0; mi < 4; mi++)
        #pragma unroll
        for (int ni = 0; ni < 4; ni++)
            #pragma unroll
            for (int c = 0; c < 4; c++) acc[mi][ni][c] = 0.f;

    const float4 z4 = make_float4(0.f, 0.f, 0.f, 0.f);
    float4 a0, a1, b0, b1;

    auto ldglob = [&](int kt) {
        int r0 = rowBase + ar, r1 = r0 + 64;
        a0 = (r0 < M) ? *(const float4*)(A + (size_t)r0 * lda + kt + kc) : z4;
        a1 = (r1 < M) ? *(const float4*)(A + (size_t)r1 * lda + kt + kc) : z4;
        b0 = *(const float4*)(B + (size_t)(kt + kb) * ldb + colBase + cb);
        b1 = *(const float4*)(B + (size_t)(kt + kb + 8) * ldb + colBase + cb);
    };
    auto stsh = [&](int buf) {
        As[buf][kc + 0][ar] = tf32(a0.x); As[buf][kc + 1][ar] = tf32(a0.y);
        As[buf][kc + 2][ar] = tf32(a0.z); As[buf][kc + 3][ar] = tf32(a0.w);
        As[buf][kc + 0][ar + 64] = tf32(a1.x); As[buf][kc + 1][ar + 64] = tf32(a1.y);
        As[buf][kc + 2][ar + 64] = tf32(a1.z); As[buf][kc + 3][ar + 64] = tf32(a1.w);
        Bs[buf][kb][cb + 0] = tf32(b0.x); Bs[buf][kb][cb + 1] = tf32(b0.y);
        Bs[buf][kb][cb + 2] = tf32(b0.z); Bs[buf][kb][cb + 3] = tf32(b0.w);
        Bs[buf][kb + 8][cb + 0] = tf32(b1.x); Bs[buf][kb + 8][cb + 1] = tf32(b1.y);
        Bs[buf][kb + 8][cb + 2] = tf32(b1.z); Bs[buf][kb + 8][cb + 3] = tf32(b1.w);
    };
    auto comp = [&](int buf) {
        #pragma unroll
        for (int k0 = 0; k0 < 16; k0 += 8) {
            unsigned af[4][4], bf[4][2];
            #pragma unroll
            for (int mi = 0; mi < 4; mi++) {
                int m0 = wm + mi * 16 + gi;
                af[mi][0] = As[buf][k0 + tg][m0];
                af[mi][1] = As[buf][k0 + tg][m0 + 8];
                af[mi][2] = As[buf][k0 + 4 + tg][m0];
                af[mi][3] = As[buf][k0 + 4 + tg][m0 + 8];
            }
            #pragma unroll
            for (int ni = 0; ni < 4; ni++) {
                int n0 = wn + ni * 8 + gi;
                bf[ni][0] = Bs[buf][k0 + tg][n0];
                bf[ni][1] = Bs[buf][k0 + 4 + tg][n0];
            }
            #pragma unroll
            for (int mi = 0; mi < 4; mi++)
                #pragma unroll
                for (int ni = 0; ni < 4; ni++)
                    mma_tf32(acc[mi][ni], af[mi], bf[ni]);
        }
    };

    ldglob(0);
    stsh(0);
    __syncthreads();
    int buf = 0;
    for (int kt = 16; kt < K; kt += 16) {
        ldglob(kt);
        comp(buf);
        stsh(buf ^ 1);
        __syncthreads();
        buf ^= 1;
    }
    comp(buf);

    #pragma unroll
    for (int mi = 0; mi < 4; mi++) {
        int r0 = rowBase + wm + mi * 16 + gi;
        int r1 = r0 + 8;
        #pragma unroll
        for (int ni = 0; ni < 4; ni++) {
            int c = colBase + wn + ni * 8 + 2 * tg;
            float2 bv = *(const float2*)(bias + c);
            bool inKV = (c >= Ckv) && (c < 3 * Ckv);
            float2 o0 = make_float2(acc[mi][ni][0] + bv.x, acc[mi][ni][1] + bv.y);
            float2 o1 = make_float2(acc[mi][ni][2] + bv.x, acc[mi][ni][3] + bv.y);
            if (inKV) {
                if (r0 < M)
                    *(__half2*)&KV[(size_t)r0 * (2 * Ckv) + (c - Ckv)] =
                        __floats2half2_rn(o0.x, o0.y);
                if (r1 < M)
                    *(__half2*)&KV[(size_t)r1 * (2 * Ckv) + (c - Ckv)] =
                        __floats2half2_rn(o1.x, o1.y);
            } else {
                if (r0 < M) *(float2*)&Cmat[(size_t)r0 * ldc + c] = o0;
                if (r1 < M) *(float2*)&Cmat[(size_t)r1 * ldc + c] = o1;
            }
        }
    }
}

// ------------------------- P[n,f] = sum_c Q[n,c] * We[f,c] -------------------
template <int C>
__global__ __launch_bounds__(256) void qe_k(
    const float* __restrict__ Q, int ld, const float* __restrict__ WeT,
    float* __restrict__ P, int n)
{
    __shared__ float WT[C * 16];
    for (int i = threadIdx.x; i < C * 16; i += 256) WT[i] = WeT[i];
    __syncthreads();

    int idx = blockIdx.x * 256 + threadIdx.x;
    int node = idx >> 4, f = idx & 15;
    if (node >= n) return;
    const float* q = Q + (size_t)node * ld;
    float acc = 0.f;
    #pragma unroll 8
    for (int c = 0; c < C; c++) acc += q[c] * WT[c * 16 + f];
    P[(size_t)node * 16 + f] = acc;
}

// ------------------------- fused attention (warp per dst, fp16 KV) -----------
template <int C, bool RELU>
__global__ __launch_bounds__(256) void fused_attn_k(
    float* __restrict__ QKVS, int ld,
    const __half* __restrict__ KV,
    const float* __restrict__ attrS, const int* __restrict__ srcS,
    const int* __restrict__ off, const float* __restrict__ P,
    const float* __restrict__ We, float isc, int n)
{
    constexpr int NV = C / 128;
    __shared__ float Ws[16 * C];
    for (int i = threadIdx.x; i < 16 * C; i += 256) Ws[i] = We[i];
    __syncthreads();

    const int node = blockIdx.x * 8 + (threadIdx.x >> 5);
    const int lane = threadIdx.x & 31;
    if (node >= n) return;

    const int e0 = off[node], e1 = off[node + 1];

    float4 q[NV];
    const float4* qb = (const float4*)(QKVS + (size_t)node * ld);
    #pragma unroll
    for (int i = 0; i < NV; i++) q[i] = qb[lane + i * 32];

    const float pP = (lane < 16) ? P[(size_t)node * 16 + lane] : 0.f;

    float m = -INFINITY, s = 0.f, tacc = 0.f;
    float4 vacc[NV];
    #pragma unroll
    for (int i = 0; i < NV; i++) vacc[i] = make_float4(0.f, 0.f, 0.f, 0.f);

    int pf_sn0 = 0, pf_sn1 = 0;
    float pf_av0 = 0.f, pf_av1 = 0.f;
    if (e0 < e1) {
        pf_sn0 = srcS[e0];
        pf_av0 = (lane < 16) ? __ldcs(&attrS[(size_t)e0 * 16 + lane]) : 0.f;
    }
    if (e0 + 1 < e1) {
        pf_sn1 = srcS[e0 + 1];
        pf_av1 = (lane < 16) ? __ldcs(&attrS[(size_t)(e0 + 1) * 16 + lane]) : 0.f;
    }

    int e = e0;
    while (e + 1 < e1) {
        const int sn0 = pf_sn0, sn1 = pf_sn1;
        const float av0 = pf_av0, av1 = pf_av1;
        if (e + 2 < e1) {
            pf_sn0 = srcS[e + 2];
            pf_av0 = (lane < 16) ? __ldcs(&attrS[(size_t)(e + 2) * 16 + lane]) : 0.f;
        }
        if (e + 3 < e1) {
            pf_sn1 = srcS[e + 3];
            pf_av1 = (lane < 16) ? __ldcs(&attrS[(size_t)(e + 3) * 16 + lane]) : 0.f;
        }

        const uint2* kv0 = (const uint2*)(KV + (size_t)sn0 * (2 * C));
        const uint2* kv1 = (const uint2*)(KV + (size_t)sn1 * (2 * C));

        uint2 ku0[NV], vu0[NV], ku1[NV], vu1[NV];
        #pragma unroll
        for (int i = 0; i < NV; i++) {
            ku0[i] = kv0[lane + i * 32];
            vu0[i] = kv0[C / 4 + lane + i * 32];
            ku1[i] = kv1[lane + i * 32];
            vu1[i] = kv1[C / 4 + lane + i * 32];
        }

        float p0 = av0 * pP, p1 = av1 * pP;
        #pragma unroll
        for (int i = 0; i < NV; i++) {
            float2 a0 = __half22float2(*(const __half2*)&ku0[i].x);
            float2 b0 = __half22float2(*(const __half2*)&ku0[i].y);
            float2 a1 = __half22float2(*(const __half2*)&ku1[i].x);
            float2 b1 = __half22float2(*(const __half2*)&ku1[i].y);
            p0 += q[i].x * a0.x + q[i].y * a0.y + q[i].z * b0.x + q[i].w * b0.y;
            p1 += q[i].x * a1.x + q[i].y * a1.y + q[i].z * b1.x + q[i].w * b1.y;
        }
        #pragma unroll
        for (int o = 16; o; o >>= 1) {
            p0 += __shfl_xor_sync(0xFFFFFFFFu, p0, o);
            p1 += __shfl_xor_sync(0xFFFFFFFFu, p1, o);
        }

        const float al0 = p0 * isc, al1 = p1 * isc;
        const float mn = fmaxf(m, fmaxf(al0, al1));
        const float corr = __expf(m - mn);
        const float w0 = __expf(al0 - mn);
        const float w1 = __expf(al1 - mn);
        m = mn;
        s = s * corr + w0 + w1;
        tacc = tacc * corr + w0 * av0 + w1 * av1;
        #pragma unroll
        for (int i = 0; i < NV; i++) {
            float2 a0 = __half22float2(*(const __half2*)&vu0[i].x);
            float2 b0 = __half22float2(*(const __half2*)&vu0[i].y);
            float2 a1 = __half22float2(*(const __half2*)&vu1[i].x);
            float2 b1 = __half22float2(*(const __half2*)&vu1[i].y);
            vacc[i].x = vacc[i].x * corr + w0 * a0.x + w1 * a1.x;
            vacc[i].y = vacc[i].y * corr + w0 * a0.y + w1 * a1.y;
            vacc[i].z = vacc[i].z * corr + w0 * b0.x + w1 * b1.x;
            vacc[i].w = vacc[i].w * corr + w0 * b0.y + w1 * b1.y;
        }
        e += 2;
    }

    if (e < e1) {
        const int sn = pf_sn0;
        const float av = pf_av0;
        const uint2* kv = (const uint2*)(KV + (size_t)sn * (2 * C));
        uint2 ku[NV], vu[NV];
        #pragma unroll
        for (int i = 0; i < NV; i++) {
            ku[i] = kv[lane + i * 32];
            vu[i] = kv[C / 4 + lane + i * 32];
        }

        float part = av * pP;
        #pragma unroll
        for (int i = 0; i < NV; i++) {
            float2 a = __half22float2(*(const __half2*)&ku[i].x);
            float2 b = __half22float2(*(const __half2*)&ku[i].y);
            part += q[i].x * a.x + q[i].y * a.y + q[i].z * b.x + q[i].w * b.y;
        }
        #pragma unroll
        for (int o = 16; o; o >>= 1) part += __shfl_xor_sync(0xFFFFFFFFu, part, o);

        const float al = part * isc;
        const float mn = fmaxf(m, al);
        const float corr = __expf(m - mn);
        const float p = __expf(al - mn);
        m = mn;
        s = s * corr + p;
        tacc = tacc * corr + p * av;
        #pragma unroll
        for (int i = 0; i < NV; i++) {
            float2 a = __half22float2(*(const __half2*)&vu[i].x);
            float2 b = __half22float2(*(const __half2*)&vu[i].y);
            vacc[i].x = vacc[i].x * corr + p * a.x;
            vacc[i].y = vacc[i].y * corr + p * a.y;
            vacc[i].z = vacc[i].z * corr + p * b.x;
            vacc[i].w = vacc[i].w * corr + p * b.y;
        }
    }

    const float inv = 1.f / (s + 1e-16f);

    float4 ed[NV];
    #pragma unroll
    for (int i = 0; i < NV; i++) ed[i] = make_float4(0.f, 0.f, 0.f, 0.f);
    #pragma unroll
    for (int f = 0; f < 16; f++) {
        const float tf = __shfl_sync(0xFFFFFFFFu, tacc, f) * inv;
        #pragma unroll
        for (int i = 0; i < NV; i++) {
            float4 w = *(const float4*)&Ws[f * C + (lane + i * 32) * 4];
            ed[i].x += tf * w.x; ed[i].y += tf * w.y;
            ed[i].z += tf * w.z; ed[i].w += tf * w.w;
        }
    }

    float4* hb = (float4*)(QKVS + (size_t)node * ld + 3 * C);
    #pragma unroll
    for (int i = 0; i < NV; i++) {
        float4 sk = hb[lane + i * 32];
        float4 o;
        o.x = sk.x + vacc[i].x * inv + ed[i].x;
        o.y = sk.y + vacc[i].y * inv + ed[i].y;
        o.z = sk.z + vacc[i].z * inv + ed[i].z;
        o.w = sk.w + vacc[i].w * inv + ed[i].w;
        if (RELU) {
            o.x = fmaxf(o.x, 0.f); o.y = fmaxf(o.y, 0.f);
            o.z = fmaxf(o.z, 0.f); o.w = fmaxf(o.w, 0.f);
        }
        hb[lane + i * 32] = o;
    }
}

// ------------------------- classifier ----------------------------------------
__global__ __launch_bounds__(256) void classifier_k(
    const float* __restrict__ H, int ldh, const float* __restrict__ Wc,
    const float* __restrict__ bc, float* __restrict__ out, int M)
{
    __shared__ float Ws[256 * 10];
    for (int i = threadIdx.x; i < 2560; i += blockDim.x) Ws[i] = Wc[i];
    __syncthreads();

    int row  = blockIdx.x * 8 + (threadIdx.x >> 5);
    int lane = threadIdx.x & 31;
    if (row >= M) return;

    float acc[10];
    #pragma unroll
    for (int c = 0; c < 10; c++) acc[c] = 0.f;

    for (int k = lane; k < 256; k += 32) {
        float h = H[(size_t)row * ldh + k];
        #pragma unroll
        for (int c = 0; c < 10; c++) acc[c] += h * Ws[k * 10 + c];
    }
    #pragma unroll
    for (int c = 0; c < 10; c++)
        #pragma unroll
        for (int o = 16; o; o >>= 1)
            acc[c] += __shfl_xor_sync(0xFFFFFFFFu, acc[c], o);

    if (lane == 0) {
        #pragma unroll
        for (int c = 0; c < 10; c++)
            out[(size_t)row * 10 + c] = acc[c] + bc[c];
    }
}

// ------------------------- launch --------------------------------------------
extern "C" void kernel_launch(void* const* d_in, const int* in_sizes, int n_in,
                              void* d_out, int out_size)
{
    const float* x    = (const float*)d_in[0];
    const int*   ei   = (const int*)d_in[1];
    const float* attr = (const float*)d_in[2];
    const int* src = ei;
    const int* dst = ei + NE;

    float *B1, *B2, *P, *Wp, *bp, *WeT, *attrS;
    __half* KV;
    int *cnt, *off, *bsum, *cursor, *srcS;
    cudaGetSymbolAddress((void**)&B1,     g_B1);
    cudaGetSymbolAddress((void**)&B2,     g_B2);
    cudaGetSymbolAddress((void**)&KV,     g_KV);
    cudaGetSymbolAddress((void**)&P,      g_P);
    cudaGetSymbolAddress((void**)&Wp,     g_Wp);
    cudaGetSymbolAddress((void**)&bp,     g_bp);
    cudaGetSymbolAddress((void**)&WeT,    g_WeT);
    cudaGetSymbolAddress((void**)&cnt,    g_cnt);
    cudaGetSymbolAddress((void**)&off,    g_off);
    cudaGetSymbolAddress((void**)&bsum,   g_bsum);
    cudaGetSymbolAddress((void**)&cursor, g_cursor);
    cudaGetSymbolAddress((void**)&srcS,   g_srcS);
    cudaGetSymbolAddress((void**)&attrS,  g_attrS);

    auto IN = [&](int i) { return (const float*)d_in[i]; };

    // ---- sort edges by dst (once; reused by all 3 layers) ----
    zero_cnt_k<<<(NN + 255) / 256, 256>>>(cnt, NN);
    hist_k<<<(NE + 255) / 256, 256>>>(dst, cnt, NE);
    scan1_k<<<SCAN_NB, SCAN_T>>>(cnt, off, bsum, NN);
    scan2_k<<<1, 128>>>(bsum, SCAN_NB);
    scan3_k<<<SCAN_NB, SCAN_T>>>(off, bsum, cursor, NN, NE);
    scatter_k<<<(NE + 255) / 256, 256>>>(src, dst, attr, cursor, srcS, attrS, NE);

    // ---- layers ----
    const float* Ain[3]  = { x, B1 + 3 * 128, B2 + 3 * 128 };
    int          lda[3]  = { 128, 512, 512 };
    int          din[3]  = { 128, 128, 128 };
    int          Cc[3]   = { 128, 128, 256 };
    float*       outb[3] = { B1, B2, B1 };
    int          ldo[3]  = { 512, 512, 1024 };

    for (int l = 0; l < 3; l++) {
        const int base = 3 + l * 9;
        const float *Wq = IN(base + 0), *bq = IN(base + 1);
        const float *Wk = IN(base + 2), *bk = IN(base + 3);
        const float *Wv = IN(base + 4), *bv = IN(base + 5);
        const float *We = IN(base + 6);
        const float *Wr = IN(base + 7), *br = IN(base + 8);
        const int C = Cc[l];
        float* out = outb[l];
        const int ld = ldo[l];

        pack_k<<<256, 256>>>(Wq, Wk, Wv, Wr, bq, bk, bv, br, We,
                             Wp, bp, WeT, din[l], C);

        dim3 gg((NN + 127) / 128, 4 * C / 128);
        sgemm_tc_k<<<gg, 256>>>(Ain[l], lda[l], Wp, 4 * C, bp, out, ld,
                                KV, C, NN, din[l]);

        if (C == 128) qe_k<128><<<(NN * 16 + 255) / 256, 256>>>(out, ld, WeT, P, NN);
        else          qe_k<256><<<(NN * 16 + 255) / 256, 256>>>(out, ld, WeT, P, NN);

        float isc = 1.0f / sqrtf((float)C);
        if (C == 128) {
            if (l < 2)
                fused_attn_k<128, true ><<<(NN + 7) / 8, 256>>>(out, ld, KV, attrS, srcS, off, P, We, isc, NN);
            else
                fused_attn_k<128, false><<<(NN + 7) / 8, 256>>>(out, ld, KV, attrS, srcS, off, P, We, isc, NN);
        } else {
            if (l < 2)
                fused_attn_k<256, true ><<<(NN + 7) / 8, 256>>>(out, ld, KV, attrS, srcS, off, P, We, isc, NN);
            else
                fused_attn_k<256, false><<<(NN + 7) / 8, 256>>>(out, ld, KV, attrS, srcS, off, P, We, isc, NN);
        }
    }

    classifier_k<<<(NN + 7) / 8, 256>>>(B1 + 768, 1024, IN(30), IN(31), (float*)d_out, NN);
}